// round 1
// baseline (speedup 1.0000x reference)
#include <cuda_runtime.h>
#include <math.h>

// Problem constants
#define BB 8
#define MM 4096
#define DD 1024
#define NEXP 64
#define PP 2
#define NP 128            // NEXP * PP
#define BM (BB * MM)      // 32768 tokens

static __device__ __constant__ float c_eps = 1e-12f;

// ---- scratch (device globals; no allocation allowed) ----
__device__ float g_phin[DD * NP];       // [d][np]  (transposed for coalesced GEMM loads)
__device__ float g_rinv[BM];            // per-token 1/(max(||x||,eps)*TEMP)
__device__ float g_E[(size_t)BM * NP];  // exp(logits)    16 MB
__device__ float g_part[BB * 32 * NP];  // partial column sums
__device__ float g_colsum[BB * NP];     // dispatch softmax denominators
__device__ float g_xs[BB * NP * DD];    // slot inputs (already /colsum)   4 MB
__device__ float g_ys[BB * NP * DD];    // expert outputs                  4 MB

// ---------------------------------------------------------------------------
__device__ __forceinline__ float warpReduceSum(float v) {
    v += __shfl_down_sync(0xffffffffu, v, 16);
    v += __shfl_down_sync(0xffffffffu, v, 8);
    v += __shfl_down_sync(0xffffffffu, v, 4);
    v += __shfl_down_sync(0xffffffffu, v, 2);
    v += __shfl_down_sync(0xffffffffu, v, 1);
    return v;
}

// K1: phin[d][np] = scale * phi[d][np] / max(||phi[:,np]||, eps)
__global__ void k_phinorm(const float* __restrict__ phi, const float* __restrict__ scale) {
    int np = blockIdx.x;
    int t = threadIdx.x;
    float s = 0.f;
    for (int d = t; d < DD; d += 256) {
        float v = phi[d * NP + np];
        s += v * v;
    }
    __shared__ float red[8];
    s = warpReduceSum(s);
    if ((t & 31) == 0) red[t >> 5] = s;
    __syncthreads();
    if (t < 32) {
        float v = (t < 8) ? red[t] : 0.f;
        v = warpReduceSum(v);
        if (t == 0) red[0] = scale[0] / fmaxf(sqrtf(v), c_eps);
    }
    __syncthreads();
    float rn = red[0];
    for (int d = t; d < DD; d += 256)
        g_phin[d * NP + np] = phi[d * NP + np] * rn;
}

// K2: g_rinv[token] = (1/TEMP) / max(||x_token||, eps)
__global__ void k_rinv(const float* __restrict__ x) {
    int tok = blockIdx.x;
    int t = threadIdx.x;
    const float4* xr = reinterpret_cast<const float4*>(x + (size_t)tok * DD);
    float4 v = xr[t];
    float s = v.x * v.x + v.y * v.y + v.z * v.z + v.w * v.w;
    __shared__ float red[8];
    s = warpReduceSum(s);
    if ((t & 31) == 0) red[t >> 5] = s;
    __syncthreads();
    if (t == 0) {
        float tot = 0.f;
        #pragma unroll
        for (int i = 0; i < 8; i++) tot += red[i];
        g_rinv[tok] = 10.0f / fmaxf(sqrtf(tot), c_eps);  // 1/TEMP = 10
    }
}

// K3: E[token][np] = exp( (x_token . phin_col) * rinv[token] )
// Tiled GEMM: 64 tokens x 128 np per block, K = 1024 in chunks of 32.
__global__ __launch_bounds__(256) void k_logits(const float* __restrict__ x) {
    __shared__ float As[64 * 32];
    __shared__ float Bs[32 * NP];
    int tok0 = blockIdx.x * 64;
    int t = threadIdx.x;
    int tr = t >> 5;   // 0..7  -> 8 tokens each
    int tc = t & 31;   // 0..31 -> 4 np each
    float acc[8][4];
    #pragma unroll
    for (int i = 0; i < 8; i++)
        #pragma unroll
        for (int j = 0; j < 4; j++) acc[i][j] = 0.f;

    for (int k0 = 0; k0 < DD; k0 += 32) {
        #pragma unroll
        for (int i = 0; i < 8; i++) {
            int lin = t + i * 256;
            int r = lin >> 5, c = lin & 31;
            As[lin] = x[(size_t)(tok0 + r) * DD + k0 + c];
        }
        #pragma unroll
        for (int i = 0; i < 16; i++) {
            int lin = t + i * 256;
            int kk = lin >> 7, np = lin & 127;
            Bs[lin] = g_phin[(k0 + kk) * NP + np];
        }
        __syncthreads();
        #pragma unroll
        for (int k = 0; k < 32; k++) {
            float a[8];
            #pragma unroll
            for (int i = 0; i < 8; i++) a[i] = As[(tr * 8 + i) * 32 + k];
            float4 bv = *reinterpret_cast<const float4*>(&Bs[k * NP + tc * 4]);
            #pragma unroll
            for (int i = 0; i < 8; i++) {
                acc[i][0] += a[i] * bv.x;
                acc[i][1] += a[i] * bv.y;
                acc[i][2] += a[i] * bv.z;
                acc[i][3] += a[i] * bv.w;
            }
        }
        __syncthreads();
    }
    #pragma unroll
    for (int i = 0; i < 8; i++) {
        int tok = tok0 + tr * 8 + i;
        float rv = g_rinv[tok];
        #pragma unroll
        for (int j = 0; j < 4; j++)
            g_E[(size_t)tok * NP + tc * 4 + j] = expf(acc[i][j] * rv);
    }
}

// K4a/K4b: deterministic column sums over m (dispatch softmax denominator)
__global__ void k_colsum_part() {
    int b = blockIdx.x, mb = blockIdx.y;
    int np = threadIdx.x;  // 128 threads
    int base = b * MM + mb * 128;
    float s = 0.f;
    for (int i = 0; i < 128; i++)
        s += g_E[(size_t)(base + i) * NP + np];
    g_part[(b * 32 + mb) * NP + np] = s;
}
__global__ void k_colsum() {
    int b = blockIdx.x;
    int np = threadIdx.x;
    float s = 0.f;
    for (int i = 0; i < 32; i++)
        s += g_part[(b * 32 + i) * NP + np];
    g_colsum[b * NP + np] = s;
}

// K5: xs[b][np][d] = (1/colsum) * sum_m E[b][m][np] * x[b][m][d]
// Block: all 128 np x 64 d, K = m (4096) in chunks of 32. Grid (16 dtiles, 8 b).
__global__ __launch_bounds__(256) void k_xs(const float* __restrict__ x) {
    __shared__ float Es[32 * NP];
    __shared__ float Xs[32 * 64];
    int b = blockIdx.y;
    int d0 = blockIdx.x * 64;
    int t = threadIdx.x;
    int tn = t >> 4;  // 0..15 -> 8 np each
    int td = t & 15;  // 0..15 -> 4 d each
    float acc[8][4];
    #pragma unroll
    for (int i = 0; i < 8; i++)
        #pragma unroll
        for (int j = 0; j < 4; j++) acc[i][j] = 0.f;

    for (int m0 = 0; m0 < MM; m0 += 32) {
        #pragma unroll
        for (int i = 0; i < 16; i++) {
            int lin = t + i * 256;
            int mm = lin >> 7, np = lin & 127;
            Es[lin] = g_E[(size_t)(b * MM + m0 + mm) * NP + np];
        }
        #pragma unroll
        for (int i = 0; i < 8; i++) {
            int lin = t + i * 256;
            int mm = lin >> 6, dd = lin & 63;
            Xs[lin] = x[(size_t)(b * MM + m0 + mm) * DD + d0 + dd];
        }
        __syncthreads();
        #pragma unroll
        for (int k = 0; k < 32; k++) {
            float a[8];
            #pragma unroll
            for (int i = 0; i < 8; i++) a[i] = Es[k * NP + tn * 8 + i];
            float4 bv = *reinterpret_cast<const float4*>(&Xs[k * 64 + td * 4]);
            #pragma unroll
            for (int i = 0; i < 8; i++) {
                acc[i][0] += a[i] * bv.x;
                acc[i][1] += a[i] * bv.y;
                acc[i][2] += a[i] * bv.z;
                acc[i][3] += a[i] * bv.w;
            }
        }
        __syncthreads();
    }
    #pragma unroll
    for (int i = 0; i < 8; i++) {
        int np = tn * 8 + i;
        float inv = 1.0f / g_colsum[b * NP + np];
        #pragma unroll
        for (int j = 0; j < 4; j++)
            g_xs[((size_t)b * NP + np) * DD + d0 + td * 4 + j] = acc[i][j] * inv;
    }
}

// K6: ys[row=(b,p)][e] = sum_d xs[row][d] * W[n][d][e] + bias[n][e], per expert n
// Block: 16 rows x 128 e, K = 1024 in chunks of 32. Grid (8 etiles, 64 n).
__global__ __launch_bounds__(256) void k_ys(const float* __restrict__ W, const float* __restrict__ bias) {
    __shared__ float As[16 * 32];
    __shared__ float Ws[32 * 128];
    int n = blockIdx.y;
    int e0 = blockIdx.x * 128;
    int t = threadIdx.x;
    int tr = t >> 5;  // 0..7 -> 2 rows each
    int tc = t & 31;  // 0..31 -> 4 e each
    float acc[2][4];
    #pragma unroll
    for (int r = 0; r < 2; r++)
        #pragma unroll
        for (int j = 0; j < 4; j++) acc[r][j] = 0.f;

    for (int k0 = 0; k0 < DD; k0 += 32) {
        #pragma unroll
        for (int i = 0; i < 2; i++) {
            int lin = t + i * 256;
            int row = lin >> 5, c = lin & 31;
            int bb = row >> 1, p = row & 1;
            As[lin] = g_xs[((size_t)bb * NP + n * 2 + p) * DD + k0 + c];
        }
        #pragma unroll
        for (int i = 0; i < 16; i++) {
            int lin = t + i * 256;
            int kk = lin >> 7, e = lin & 127;
            Ws[lin] = W[((size_t)n * DD + k0 + kk) * DD + e0 + e];
        }
        __syncthreads();
        #pragma unroll
        for (int k = 0; k < 32; k++) {
            float a0 = As[(tr * 2 + 0) * 32 + k];
            float a1 = As[(tr * 2 + 1) * 32 + k];
            float4 bv = *reinterpret_cast<const float4*>(&Ws[k * 128 + tc * 4]);
            acc[0][0] += a0 * bv.x; acc[0][1] += a0 * bv.y;
            acc[0][2] += a0 * bv.z; acc[0][3] += a0 * bv.w;
            acc[1][0] += a1 * bv.x; acc[1][1] += a1 * bv.y;
            acc[1][2] += a1 * bv.z; acc[1][3] += a1 * bv.w;
        }
        __syncthreads();
    }
    #pragma unroll
    for (int r = 0; r < 2; r++) {
        int row = tr * 2 + r;
        int bb = row >> 1, p = row & 1;
        #pragma unroll
        for (int j = 0; j < 4; j++) {
            int e = e0 + tc * 4 + j;
            g_ys[((size_t)bb * NP + n * 2 + p) * DD + e] = acc[r][j] + bias[n * DD + e];
        }
    }
}

// K7: y[b][m][d] = x[b][m][d] + sum_np (E[b][m][np]/rowsum) * ys[b][np][d]
// Block: 32 tokens, all 1024 d in 4 chunks of 256. Grid (128 token-tiles, 8 b).
__global__ __launch_bounds__(256) void k_combine(const float* __restrict__ x, float* __restrict__ y) {
    __shared__ float Ec[32 * 132];  // padded rows (128+4) to break bank conflicts
    __shared__ float rs[32];
    int b = blockIdx.y;
    int tok0 = blockIdx.x * 32;
    int t = threadIdx.x;

    #pragma unroll
    for (int i = 0; i < 16; i++) {
        int lin = t + i * 256;
        int tk = lin >> 7, np = lin & 127;
        Ec[tk * 132 + np] = g_E[(size_t)(b * MM + tok0 + tk) * NP + np];
    }
    __syncthreads();
    if (t < 32) {
        float s = 0.f;
        #pragma unroll 8
        for (int np = 0; np < 128; np++) s += Ec[t * 132 + np];
        rs[t] = 1.0f / s;
    }
    __syncthreads();
    #pragma unroll
    for (int i = 0; i < 16; i++) {
        int lin = t + i * 256;
        int tk = lin >> 7, np = lin & 127;
        Ec[tk * 132 + np] *= rs[tk];
    }
    __syncthreads();

    for (int ch = 0; ch < 4; ch++) {
        int d = ch * 256 + t;
        float acc[32];
        #pragma unroll
        for (int tk = 0; tk < 32; tk++) acc[tk] = 0.f;
        for (int np4 = 0; np4 < 32; np4++) {
            float yv0 = g_ys[((size_t)b * NP + np4 * 4 + 0) * DD + d];
            float yv1 = g_ys[((size_t)b * NP + np4 * 4 + 1) * DD + d];
            float yv2 = g_ys[((size_t)b * NP + np4 * 4 + 2) * DD + d];
            float yv3 = g_ys[((size_t)b * NP + np4 * 4 + 3) * DD + d];
            #pragma unroll
            for (int tk = 0; tk < 32; tk++) {
                float4 c4 = *reinterpret_cast<const float4*>(&Ec[tk * 132 + np4 * 4]);
                acc[tk] += c4.x * yv0 + c4.y * yv1 + c4.z * yv2 + c4.w * yv3;
            }
        }
        #pragma unroll
        for (int tk = 0; tk < 32; tk++) {
            size_t idx = (size_t)(b * MM + tok0 + tk) * DD + d;
            y[idx] = acc[tk] + x[idx];
        }
    }
}

// ---------------------------------------------------------------------------
extern "C" void kernel_launch(void* const* d_in, const int* in_sizes, int n_in,
                              void* d_out, int out_size) {
    const float* x     = (const float*)d_in[0];  // [8,4096,1024]
    const float* phi   = (const float*)d_in[1];  // [1024,64,2]
    const float* scale = (const float*)d_in[2];  // [1]
    const float* W     = (const float*)d_in[3];  // [64,1024,1024]
    const float* bias  = (const float*)d_in[4];  // [64,1024]
    float* y = (float*)d_out;                    // [8,4096,1024]

    k_phinorm<<<NP, 256>>>(phi, scale);
    k_rinv<<<BM, 256>>>(x);
    k_logits<<<BM / 64, 256>>>(x);
    k_colsum_part<<<dim3(BB, 32), 128>>>();
    k_colsum<<<BB, NP>>>();
    k_xs<<<dim3(16, BB), 256>>>(x);
    k_ys<<<dim3(8, NEXP), 256>>>(W, bias);
    k_combine<<<dim3(MM / 32, BB), 256>>>(x, y);
}

// round 2
// speedup vs baseline: 1.2871x; 1.2871x over previous
#include <cuda_runtime.h>
#include <math.h>

// Problem constants
#define BB 8
#define MM 4096
#define DD 1024
#define NEXP 64
#define PP 2
#define NP 128            // NEXP * PP
#define BM (BB * MM)      // 32768 tokens

static __device__ __constant__ float c_eps = 1e-12f;

// ---- scratch (device globals; no allocation allowed) ----
__device__ float g_phin[DD * NP];       // [d][np]
__device__ float g_rinv[BM];            // per-token (1/TEMP)/max(||x||,eps)
__device__ float g_E[(size_t)BM * NP];  // exp(logits)  16 MB
__device__ float g_part[BB * 64 * NP];  // partial column sums
__device__ float g_colsum[BB * NP];     // dispatch softmax denominators
__device__ float g_xs[BB * NP * DD];    // slot inputs (already /colsum)
__device__ float g_ys[BB * NP * DD];    // expert outputs

// packed dual-fp32 FMA: d = a*b + d  (SASS FFMA2, 2 FMAs/lane/inst)
__device__ __forceinline__ void ffma2(float2& d, const float2 a, const float2 b) {
    asm("fma.rn.f32x2 %0, %1, %2, %0;"
        : "+l"(reinterpret_cast<unsigned long long&>(const_cast<float2&>(d)))
        : "l"(reinterpret_cast<const unsigned long long&>(a)),
          "l"(reinterpret_cast<const unsigned long long&>(b)));
}

__device__ __forceinline__ float warpReduceSum(float v) {
    v += __shfl_down_sync(0xffffffffu, v, 16);
    v += __shfl_down_sync(0xffffffffu, v, 8);
    v += __shfl_down_sync(0xffffffffu, v, 4);
    v += __shfl_down_sync(0xffffffffu, v, 2);
    v += __shfl_down_sync(0xffffffffu, v, 1);
    return v;
}

// K1: phin[d][np] = scale * phi[d][np] / max(||phi[:,np]||, eps)
__global__ void k_phinorm(const float* __restrict__ phi, const float* __restrict__ scale) {
    int np = blockIdx.x;
    int t = threadIdx.x;
    float s = 0.f;
    for (int d = t; d < DD; d += 256) {
        float v = phi[d * NP + np];
        s += v * v;
    }
    __shared__ float red[8];
    s = warpReduceSum(s);
    if ((t & 31) == 0) red[t >> 5] = s;
    __syncthreads();
    if (t < 32) {
        float v = (t < 8) ? red[t] : 0.f;
        v = warpReduceSum(v);
        if (t == 0) red[0] = scale[0] / fmaxf(sqrtf(v), c_eps);
    }
    __syncthreads();
    float rn = red[0];
    for (int d = t; d < DD; d += 256)
        g_phin[d * NP + np] = phi[d * NP + np] * rn;
}

// K2: warp-per-token row norms. 8 tokens per block.
__global__ void k_rinv(const float* __restrict__ x) {
    int w = threadIdx.x >> 5;
    int lane = threadIdx.x & 31;
    int tok = blockIdx.x * 8 + w;
    const float4* xr = reinterpret_cast<const float4*>(x + (size_t)tok * DD);
    float s = 0.f;
    #pragma unroll
    for (int i = 0; i < 8; i++) {
        float4 v = xr[lane + i * 32];
        s += v.x * v.x + v.y * v.y + v.z * v.z + v.w * v.w;
    }
    s = warpReduceSum(s);
    if (lane == 0) g_rinv[tok] = 10.0f / fmaxf(sqrtf(s), c_eps);  // 1/TEMP = 10
}

// K3: E[token][np] = exp( (x_token . phin_col) * rinv[token] )
// 64 tokens x 128 np per block, K = 1024 in chunks of 32. FFMA2 inner loop.
__global__ __launch_bounds__(256) void k_logits(const float* __restrict__ x) {
    __shared__ float As[64 * 32];
    __shared__ float Bs[32 * NP];
    int tok0 = blockIdx.x * 64;
    int t = threadIdx.x;
    int tr = t >> 5;   // warp id: 8 tokens each
    int tc = t & 31;   // lane: 4 np each
    float2 acc[8][2];
    #pragma unroll
    for (int i = 0; i < 8; i++) {
        acc[i][0] = make_float2(0.f, 0.f);
        acc[i][1] = make_float2(0.f, 0.f);
    }

    for (int k0 = 0; k0 < DD; k0 += 32) {
        #pragma unroll
        for (int i = 0; i < 8; i++) {
            int lin = t + i * 256;
            int r = lin >> 5, c = lin & 31;
            As[lin] = x[(size_t)(tok0 + r) * DD + k0 + c];
        }
        #pragma unroll
        for (int i = 0; i < 16; i++) {
            int lin = t + i * 256;
            int kk = lin >> 7, np = lin & 127;
            Bs[lin] = g_phin[(k0 + kk) * NP + np];
        }
        __syncthreads();
        #pragma unroll
        for (int k = 0; k < 32; k++) {
            float4 bv = *reinterpret_cast<const float4*>(&Bs[k * NP + tc * 4]);
            float2 b0 = make_float2(bv.x, bv.y);
            float2 b1 = make_float2(bv.z, bv.w);
            #pragma unroll
            for (int i = 0; i < 8; i++) {
                float a = As[(tr * 8 + i) * 32 + k];
                float2 ap = make_float2(a, a);
                ffma2(acc[i][0], ap, b0);
                ffma2(acc[i][1], ap, b1);
            }
        }
        __syncthreads();
    }
    #pragma unroll
    for (int i = 0; i < 8; i++) {
        int tok = tok0 + tr * 8 + i;
        float rv = g_rinv[tok];
        float4 o;
        o.x = expf(acc[i][0].x * rv);
        o.y = expf(acc[i][0].y * rv);
        o.z = expf(acc[i][1].x * rv);
        o.w = expf(acc[i][1].y * rv);
        *reinterpret_cast<float4*>(&g_E[(size_t)tok * NP + tc * 4]) = o;
    }
}

// K4a/K4b: deterministic column sums over m (dispatch softmax denominator)
__global__ void k_colsum_part() {
    int b = blockIdx.x, mb = blockIdx.y;
    int np = threadIdx.x;  // 128 threads
    int base = b * MM + mb * 64;
    float s = 0.f;
    #pragma unroll 4
    for (int i = 0; i < 64; i++)
        s += g_E[(size_t)(base + i) * NP + np];
    g_part[(b * 64 + mb) * NP + np] = s;
}
__global__ void k_colsum() {
    int b = blockIdx.x;
    int np = threadIdx.x;
    float s = 0.f;
    #pragma unroll
    for (int i = 0; i < 64; i++)
        s += g_part[(b * 64 + i) * NP + np];
    g_colsum[b * NP + np] = s;
}

// K5: xs[b][np][d] = (1/colsum) * sum_m E[b][m][np] * x[b][m][d]
__global__ __launch_bounds__(256) void k_xs(const float* __restrict__ x) {
    __shared__ float Es[32 * NP];
    __shared__ float Xs[32 * 64];
    int b = blockIdx.y;
    int d0 = blockIdx.x * 64;
    int t = threadIdx.x;
    int tn = t >> 4;  // 16 groups: 8 np each
    int td = t & 15;  // 4 d each
    float2 acc[8][2];
    #pragma unroll
    for (int i = 0; i < 8; i++) {
        acc[i][0] = make_float2(0.f, 0.f);
        acc[i][1] = make_float2(0.f, 0.f);
    }

    for (int m0 = 0; m0 < MM; m0 += 32) {
        #pragma unroll
        for (int i = 0; i < 16; i++) {
            int lin = t + i * 256;
            int mm = lin >> 7, np = lin & 127;
            Es[lin] = g_E[(size_t)(b * MM + m0 + mm) * NP + np];
        }
        #pragma unroll
        for (int i = 0; i < 8; i++) {
            int lin = t + i * 256;
            int mm = lin >> 6, dd = lin & 63;
            Xs[lin] = x[(size_t)(b * MM + m0 + mm) * DD + d0 + dd];
        }
        __syncthreads();
        #pragma unroll
        for (int k = 0; k < 32; k++) {
            float4 bv = *reinterpret_cast<const float4*>(&Xs[k * 64 + td * 4]);
            float2 b0 = make_float2(bv.x, bv.y);
            float2 b1 = make_float2(bv.z, bv.w);
            #pragma unroll
            for (int i = 0; i < 8; i++) {
                float a = Es[k * NP + tn * 8 + i];
                float2 ap = make_float2(a, a);
                ffma2(acc[i][0], ap, b0);
                ffma2(acc[i][1], ap, b1);
            }
        }
        __syncthreads();
    }
    #pragma unroll
    for (int i = 0; i < 8; i++) {
        int np = tn * 8 + i;
        float inv = 1.0f / g_colsum[b * NP + np];
        float4 o;
        o.x = acc[i][0].x * inv;
        o.y = acc[i][0].y * inv;
        o.z = acc[i][1].x * inv;
        o.w = acc[i][1].y * inv;
        *reinterpret_cast<float4*>(&g_xs[((size_t)b * NP + np) * DD + d0 + td * 4]) = o;
    }
}

// K6: ys[row=(b,p)][e] = sum_d xs[row][d] * W[n][d][e] + bias[n][e], per expert n
__global__ __launch_bounds__(256) void k_ys(const float* __restrict__ W, const float* __restrict__ bias) {
    __shared__ float As[16 * 32];
    __shared__ float Ws[32 * 128];
    int n = blockIdx.y;
    int e0 = blockIdx.x * 128;
    int t = threadIdx.x;
    int tr = t >> 5;  // 2 rows each
    int tc = t & 31;  // 4 e each
    float2 acc[2][2];
    #pragma unroll
    for (int r = 0; r < 2; r++) {
        acc[r][0] = make_float2(0.f, 0.f);
        acc[r][1] = make_float2(0.f, 0.f);
    }

    for (int k0 = 0; k0 < DD; k0 += 32) {
        #pragma unroll
        for (int i = 0; i < 2; i++) {
            int lin = t + i * 256;
            int row = lin >> 5, c = lin & 31;
            int bb = row >> 1, p = row & 1;
            As[lin] = g_xs[((size_t)bb * NP + n * 2 + p) * DD + k0 + c];
        }
        #pragma unroll
        for (int i = 0; i < 16; i++) {
            int lin = t + i * 256;
            int kk = lin >> 7, e = lin & 127;
            Ws[lin] = W[((size_t)n * DD + k0 + kk) * DD + e0 + e];
        }
        __syncthreads();
        #pragma unroll
        for (int k = 0; k < 32; k++) {
            float4 bv = *reinterpret_cast<const float4*>(&Ws[k * 128 + tc * 4]);
            float2 b0 = make_float2(bv.x, bv.y);
            float2 b1 = make_float2(bv.z, bv.w);
            float a0 = As[(tr * 2 + 0) * 32 + k];
            float a1 = As[(tr * 2 + 1) * 32 + k];
            float2 a0p = make_float2(a0, a0);
            float2 a1p = make_float2(a1, a1);
            ffma2(acc[0][0], a0p, b0);
            ffma2(acc[0][1], a0p, b1);
            ffma2(acc[1][0], a1p, b0);
            ffma2(acc[1][1], a1p, b1);
        }
        __syncthreads();
    }
    #pragma unroll
    for (int r = 0; r < 2; r++) {
        int row = tr * 2 + r;
        int bb = row >> 1, p = row & 1;
        int e = e0 + tc * 4;
        float4 bsv = *reinterpret_cast<const float4*>(&bias[n * DD + e]);
        float4 o;
        o.x = acc[r][0].x + bsv.x;
        o.y = acc[r][0].y + bsv.y;
        o.z = acc[r][1].x + bsv.z;
        o.w = acc[r][1].y + bsv.w;
        *reinterpret_cast<float4*>(&g_ys[((size_t)bb * NP + n * 2 + p) * DD + e]) = o;
    }
}

// K7: y[b][m][d] = x[b][m][d] + sum_np (E[b][m][np]/rowsum) * ys[b][np][d]
// Block: 32 tokens, each thread owns 2 consecutive d, two 512-wide chunks.
__global__ __launch_bounds__(256) void k_combine(const float* __restrict__ x, float* __restrict__ y) {
    __shared__ float Ec[32 * 132];  // padded rows
    __shared__ float rs[32];
    int b = blockIdx.y;
    int tok0 = blockIdx.x * 32;
    int t = threadIdx.x;
    int w = t >> 5, lane = t & 31;

    #pragma unroll
    for (int i = 0; i < 16; i++) {
        int lin = t + i * 256;
        int tk = lin >> 7, np = lin & 127;
        Ec[tk * 132 + np] = g_E[(size_t)(b * MM + tok0 + tk) * NP + np];
    }
    __syncthreads();
    // warp-parallel row sums: warp w handles tokens w*4..w*4+3
    #pragma unroll
    for (int j = 0; j < 4; j++) {
        int tk = w * 4 + j;
        float s = Ec[tk * 132 + lane] + Ec[tk * 132 + lane + 32] +
                  Ec[tk * 132 + lane + 64] + Ec[tk * 132 + lane + 96];
        s = warpReduceSum(s);
        if (lane == 0) rs[tk] = 1.0f / s;
    }
    __syncthreads();
    #pragma unroll
    for (int i = 0; i < 16; i++) {
        int lin = t + i * 256;
        int tk = lin >> 7, np = lin & 127;
        Ec[tk * 132 + np] *= rs[tk];
    }
    __syncthreads();

    for (int ch = 0; ch < 2; ch++) {
        int d = ch * 512 + t * 2;
        float2 acc[32];
        #pragma unroll
        for (int tk = 0; tk < 32; tk++) acc[tk] = make_float2(0.f, 0.f);
        for (int np4 = 0; np4 < 32; np4++) {
            const float* yb = &g_ys[((size_t)b * NP + np4 * 4) * DD + d];
            float2 y0 = *reinterpret_cast<const float2*>(yb);
            float2 y1 = *reinterpret_cast<const float2*>(yb + DD);
            float2 y2 = *reinterpret_cast<const float2*>(yb + 2 * DD);
            float2 y3 = *reinterpret_cast<const float2*>(yb + 3 * DD);
            #pragma unroll
            for (int tk = 0; tk < 32; tk++) {
                float4 c4 = *reinterpret_cast<const float4*>(&Ec[tk * 132 + np4 * 4]);
                ffma2(acc[tk], make_float2(c4.x, c4.x), y0);
                ffma2(acc[tk], make_float2(c4.y, c4.y), y1);
                ffma2(acc[tk], make_float2(c4.z, c4.z), y2);
                ffma2(acc[tk], make_float2(c4.w, c4.w), y3);
            }
        }
        #pragma unroll
        for (int tk = 0; tk < 32; tk++) {
            size_t idx = (size_t)(b * MM + tok0 + tk) * DD + d;
            float2 xv = *reinterpret_cast<const float2*>(&x[idx]);
            float2 o = make_float2(acc[tk].x + xv.x, acc[tk].y + xv.y);
            *reinterpret_cast<float2*>(&y[idx]) = o;
        }
    }
}

// ---------------------------------------------------------------------------
extern "C" void kernel_launch(void* const* d_in, const int* in_sizes, int n_in,
                              void* d_out, int out_size) {
    const float* x     = (const float*)d_in[0];  // [8,4096,1024]
    const float* phi   = (const float*)d_in[1];  // [1024,64,2]
    const float* scale = (const float*)d_in[2];  // [1]
    const float* W     = (const float*)d_in[3];  // [64,1024,1024]
    const float* bias  = (const float*)d_in[4];  // [64,1024]
    float* y = (float*)d_out;                    // [8,4096,1024]

    k_phinorm<<<NP, 256>>>(phi, scale);
    k_rinv<<<BM / 8, 256>>>(x);
    k_logits<<<BM / 64, 256>>>(x);
    k_colsum_part<<<dim3(BB, 64), 128>>>();
    k_colsum<<<BB, NP>>>();
    k_xs<<<dim3(16, BB), 256>>>(x);
    k_ys<<<dim3(8, NEXP), 256>>>(W, bias);
    k_combine<<<dim3(MM / 32, BB), 256>>>(x, y);
}

// round 3
// speedup vs baseline: 1.4247x; 1.1069x over previous
#include <cuda_runtime.h>
#include <math.h>

// Problem constants
#define BB 8
#define MM 4096
#define DD 1024
#define NEXP 64
#define PP 2
#define NP 128            // NEXP * PP
#define BM (BB * MM)      // 32768 tokens

static __device__ __constant__ float c_eps = 1e-12f;

// ---- scratch (device globals; no allocation allowed) ----
__device__ float g_phin[DD * NP];            // [d][np]
__device__ float g_rinv[BM];                 // per-token (1/TEMP)/max(||x||,eps)
__device__ float g_E[(size_t)BM * NP];       // exp(logits)  16 MB
__device__ float g_part[BB * 64 * NP];       // partial column sums
__device__ float g_colsum[BB * NP];          // dispatch softmax denominators
__device__ float g_rsinv[BM];                // 1/rowsum (combine softmax denominators)
__device__ float g_xsp[4 * BB * NP * DD];    // partial slot inputs (4 m-segments) 16 MB
__device__ float g_xs[BB * NP * DD];         // slot inputs (already /colsum)
__device__ float g_ys[BB * NP * DD];         // expert outputs

// packed dual-fp32 FMA: d = a*b + d  (SASS FFMA2, 2 FMAs/lane/inst)
__device__ __forceinline__ void ffma2(float2& d, const float2 a, const float2 b) {
    asm("fma.rn.f32x2 %0, %1, %2, %0;"
        : "+l"(reinterpret_cast<unsigned long long&>(const_cast<float2&>(d)))
        : "l"(reinterpret_cast<const unsigned long long&>(a)),
          "l"(reinterpret_cast<const unsigned long long&>(b)));
}

__device__ __forceinline__ float ex2f(float x) {
    float r;
    asm("ex2.approx.f32 %0, %1;" : "=f"(r) : "f"(x));
    return r;
}

__device__ __forceinline__ float warpReduceSum(float v) {
    v += __shfl_down_sync(0xffffffffu, v, 16);
    v += __shfl_down_sync(0xffffffffu, v, 8);
    v += __shfl_down_sync(0xffffffffu, v, 4);
    v += __shfl_down_sync(0xffffffffu, v, 2);
    v += __shfl_down_sync(0xffffffffu, v, 1);
    return v;
}

// K1: phin[d][np] = scale * phi[d][np] / max(||phi[:,np]||, eps)
__global__ void k_phinorm(const float* __restrict__ phi, const float* __restrict__ scale) {
    int np = blockIdx.x;
    int t = threadIdx.x;
    float s = 0.f;
    for (int d = t; d < DD; d += 256) {
        float v = phi[d * NP + np];
        s += v * v;
    }
    __shared__ float red[8];
    s = warpReduceSum(s);
    if ((t & 31) == 0) red[t >> 5] = s;
    __syncthreads();
    if (t < 32) {
        float v = (t < 8) ? red[t] : 0.f;
        v = warpReduceSum(v);
        if (t == 0) red[0] = scale[0] / fmaxf(sqrtf(v), c_eps);
    }
    __syncthreads();
    float rn = red[0];
    for (int d = t; d < DD; d += 256)
        g_phin[d * NP + np] = phi[d * NP + np] * rn;
}

// K2: warp-per-token row norms. 8 tokens per block.
__global__ void k_rinv(const float* __restrict__ x) {
    int w = threadIdx.x >> 5;
    int lane = threadIdx.x & 31;
    int tok = blockIdx.x * 8 + w;
    const float4* xr = reinterpret_cast<const float4*>(x + (size_t)tok * DD);
    float s = 0.f;
    #pragma unroll
    for (int i = 0; i < 8; i++) {
        float4 v = xr[lane + i * 32];
        s += v.x * v.x + v.y * v.y + v.z * v.z + v.w * v.w;
    }
    s = warpReduceSum(s);
    if (lane == 0) g_rinv[tok] = 10.0f / fmaxf(sqrtf(s), c_eps);  // 1/TEMP = 10
}

// K3: E[token][np] = exp2( (x_token . phin_col) * rinv[token] * log2e )
// CTA tile: 128 tokens x 128 np, thread tile 8x8, K chunks of 32.
__global__ __launch_bounds__(256, 2) void k_logits(const float* __restrict__ x) {
    __shared__ float As[128 * 32];   // [row][k]
    __shared__ float Bs[32 * 128];   // [k][np]
    int tok0 = blockIdx.x * 128;
    int t = threadIdx.x;
    int ti = t >> 4;   // 0..15 -> rows 8*ti..
    int tj = t & 15;   // 0..15 -> cols 8*tj..
    float2 acc[8][4];
    #pragma unroll
    for (int r = 0; r < 8; r++)
        #pragma unroll
        for (int c = 0; c < 4; c++) acc[r][c] = make_float2(0.f, 0.f);

    for (int k0 = 0; k0 < DD; k0 += 32) {
        #pragma unroll
        for (int i = 0; i < 4; i++) {
            int idx = t + i * 256;
            int row = idx >> 3, kq = idx & 7;
            *reinterpret_cast<float4*>(&As[row * 32 + kq * 4]) =
                *reinterpret_cast<const float4*>(&x[(size_t)(tok0 + row) * DD + k0 + kq * 4]);
        }
        #pragma unroll
        for (int i = 0; i < 4; i++) {
            int idx = t + i * 256;
            int kk = idx >> 5, q = idx & 31;
            *reinterpret_cast<float4*>(&Bs[kk * 128 + q * 4]) =
                *reinterpret_cast<const float4*>(&g_phin[(k0 + kk) * NP + q * 4]);
        }
        __syncthreads();
        #pragma unroll
        for (int k = 0; k < 32; k++) {
            float4 b0 = *reinterpret_cast<const float4*>(&Bs[k * 128 + tj * 8]);
            float4 b1 = *reinterpret_cast<const float4*>(&Bs[k * 128 + tj * 8 + 4]);
            float2 p0 = make_float2(b0.x, b0.y), p1 = make_float2(b0.z, b0.w);
            float2 p2 = make_float2(b1.x, b1.y), p3 = make_float2(b1.z, b1.w);
            #pragma unroll
            for (int r = 0; r < 8; r++) {
                float a = As[(ti * 8 + r) * 32 + k];
                float2 ap = make_float2(a, a);
                ffma2(acc[r][0], ap, p0);
                ffma2(acc[r][1], ap, p1);
                ffma2(acc[r][2], ap, p2);
                ffma2(acc[r][3], ap, p3);
            }
        }
        __syncthreads();
    }
    #pragma unroll
    for (int r = 0; r < 8; r++) {
        int tok = tok0 + ti * 8 + r;
        float rv = g_rinv[tok] * 1.4426950408889634f;  // fold log2(e)
        float4 o0, o1;
        o0.x = ex2f(acc[r][0].x * rv);
        o0.y = ex2f(acc[r][0].y * rv);
        o0.z = ex2f(acc[r][1].x * rv);
        o0.w = ex2f(acc[r][1].y * rv);
        o1.x = ex2f(acc[r][2].x * rv);
        o1.y = ex2f(acc[r][2].y * rv);
        o1.z = ex2f(acc[r][3].x * rv);
        o1.w = ex2f(acc[r][3].y * rv);
        float* dst = &g_E[(size_t)tok * NP + tj * 8];
        *reinterpret_cast<float4*>(dst) = o0;
        *reinterpret_cast<float4*>(dst + 4) = o1;
    }
}

// K4a/K4b: deterministic column sums over m (dispatch softmax denominator)
__global__ void k_colsum_part() {
    int b = blockIdx.x, mb = blockIdx.y;
    int np = threadIdx.x;  // 128 threads
    int base = b * MM + mb * 64;
    float s = 0.f;
    #pragma unroll 4
    for (int i = 0; i < 64; i++)
        s += g_E[(size_t)(base + i) * NP + np];
    g_part[(b * 64 + mb) * NP + np] = s;
}
__global__ void k_colsum() {
    int b = blockIdx.x;
    int np = threadIdx.x;
    float s = 0.f;
    #pragma unroll
    for (int i = 0; i < 64; i++)
        s += g_part[(b * 64 + i) * NP + np];
    g_colsum[b * NP + np] = s;
}

// K4c: 1/rowsum per token (combine softmax denominator). Warp per token.
__global__ void k_rowsum() {
    int w = threadIdx.x >> 5;
    int lane = threadIdx.x & 31;
    int tok = blockIdx.x * 8 + w;
    float4 v = *reinterpret_cast<const float4*>(&g_E[(size_t)tok * NP + lane * 4]);
    float s = v.x + v.y + v.z + v.w;
    s = warpReduceSum(s);
    if (lane == 0) g_rsinv[tok] = 1.0f / s;
}

// K5: partial xs over m-segment: xsp[s][b][np][d] = sum_{m in seg} E[b][m][np] * x[b][m][d]
// CTA tile: 128 np x 128 d, thread 8x8, K (m) chunks of 32. Grid (8 dtiles, 8 b, 4 seg).
__global__ __launch_bounds__(256, 2) void k_xs(const float* __restrict__ x) {
    __shared__ float Es[32 * 128];   // [m][np]
    __shared__ float Xs[32 * 128];   // [m][d]
    int b = blockIdx.y;
    int d0 = blockIdx.x * 128;
    int seg = blockIdx.z;
    int base = b * MM + seg * 1024;
    int t = threadIdx.x;
    int ti = t >> 4;   // np rows 8*ti..
    int tj = t & 15;   // d cols 8*tj..
    float2 acc[8][4];
    #pragma unroll
    for (int r = 0; r < 8; r++)
        #pragma unroll
        for (int c = 0; c < 4; c++) acc[r][c] = make_float2(0.f, 0.f);

    for (int m0 = 0; m0 < 1024; m0 += 32) {
        #pragma unroll
        for (int i = 0; i < 4; i++) {
            int idx = t + i * 256;
            int mm = idx >> 5, q = idx & 31;
            *reinterpret_cast<float4*>(&Es[mm * 128 + q * 4]) =
                *reinterpret_cast<const float4*>(&g_E[(size_t)(base + m0 + mm) * NP + q * 4]);
        }
        #pragma unroll
        for (int i = 0; i < 4; i++) {
            int idx = t + i * 256;
            int mm = idx >> 5, q = idx & 31;
            *reinterpret_cast<float4*>(&Xs[mm * 128 + q * 4]) =
                *reinterpret_cast<const float4*>(&x[(size_t)(base + m0 + mm) * DD + d0 + q * 4]);
        }
        __syncthreads();
        #pragma unroll
        for (int k = 0; k < 32; k++) {
            float4 a0 = *reinterpret_cast<const float4*>(&Es[k * 128 + ti * 8]);
            float4 a1 = *reinterpret_cast<const float4*>(&Es[k * 128 + ti * 8 + 4]);
            float4 b0 = *reinterpret_cast<const float4*>(&Xs[k * 128 + tj * 8]);
            float4 b1 = *reinterpret_cast<const float4*>(&Xs[k * 128 + tj * 8 + 4]);
            float2 p0 = make_float2(b0.x, b0.y), p1 = make_float2(b0.z, b0.w);
            float2 p2 = make_float2(b1.x, b1.y), p3 = make_float2(b1.z, b1.w);
            float av[8] = {a0.x, a0.y, a0.z, a0.w, a1.x, a1.y, a1.z, a1.w};
            #pragma unroll
            for (int r = 0; r < 8; r++) {
                float2 ap = make_float2(av[r], av[r]);
                ffma2(acc[r][0], ap, p0);
                ffma2(acc[r][1], ap, p1);
                ffma2(acc[r][2], ap, p2);
                ffma2(acc[r][3], ap, p3);
            }
        }
        __syncthreads();
    }
    #pragma unroll
    for (int r = 0; r < 8; r++) {
        int np = ti * 8 + r;
        float* dst = &g_xsp[(((size_t)seg * BB + b) * NP + np) * DD + d0 + tj * 8];
        float4 o0, o1;
        o0.x = acc[r][0].x; o0.y = acc[r][0].y; o0.z = acc[r][1].x; o0.w = acc[r][1].y;
        o1.x = acc[r][2].x; o1.y = acc[r][2].y; o1.z = acc[r][3].x; o1.w = acc[r][3].y;
        *reinterpret_cast<float4*>(dst) = o0;
        *reinterpret_cast<float4*>(dst + 4) = o1;
    }
}

// K5b: xs = (sum_s xsp) / colsum
__global__ void k_xs_reduce() {
    int row = blockIdx.x;          // b*NP + np
    int b = row >> 7, np = row & 127;
    int t = threadIdx.x;
    float inv = 1.0f / g_colsum[b * NP + np];
    size_t off = ((size_t)b * NP + np) * DD + t * 4;
    float4 s = *reinterpret_cast<const float4*>(&g_xsp[off]);
    #pragma unroll
    for (int seg = 1; seg < 4; seg++) {
        float4 v = *reinterpret_cast<const float4*>(&g_xsp[(size_t)seg * BB * NP * DD + off]);
        s.x += v.x; s.y += v.y; s.z += v.z; s.w += v.w;
    }
    s.x *= inv; s.y *= inv; s.z *= inv; s.w *= inv;
    *reinterpret_cast<float4*>(&g_xs[off]) = s;
}

// K6: ys[row=(b,p)][e] = sum_d xs[row][d] * W[n][d][e] + bias[n][e], per expert n
__global__ __launch_bounds__(256) void k_ys(const float* __restrict__ W, const float* __restrict__ bias) {
    __shared__ float As[16 * 32];
    __shared__ float Ws[32 * 128];
    int n = blockIdx.y;
    int e0 = blockIdx.x * 128;
    int t = threadIdx.x;
    int tr = t >> 5;  // 2 rows each
    int tc = t & 31;  // 4 e each
    float2 acc[2][2];
    #pragma unroll
    for (int r = 0; r < 2; r++) {
        acc[r][0] = make_float2(0.f, 0.f);
        acc[r][1] = make_float2(0.f, 0.f);
    }

    for (int k0 = 0; k0 < DD; k0 += 32) {
        #pragma unroll
        for (int i = 0; i < 2; i++) {
            int lin = t + i * 256;
            int row = lin >> 5, c = lin & 31;
            int bb = row >> 1, p = row & 1;
            As[lin] = g_xs[((size_t)bb * NP + n * 2 + p) * DD + k0 + c];
        }
        #pragma unroll
        for (int i = 0; i < 16; i++) {
            int lin = t + i * 256;
            int kk = lin >> 7, e = lin & 127;
            Ws[lin] = W[((size_t)n * DD + k0 + kk) * DD + e0 + e];
        }
        __syncthreads();
        #pragma unroll
        for (int k = 0; k < 32; k++) {
            float4 bv = *reinterpret_cast<const float4*>(&Ws[k * 128 + tc * 4]);
            float2 b0 = make_float2(bv.x, bv.y);
            float2 b1 = make_float2(bv.z, bv.w);
            float a0 = As[(tr * 2 + 0) * 32 + k];
            float a1 = As[(tr * 2 + 1) * 32 + k];
            float2 a0p = make_float2(a0, a0);
            float2 a1p = make_float2(a1, a1);
            ffma2(acc[0][0], a0p, b0);
            ffma2(acc[0][1], a0p, b1);
            ffma2(acc[1][0], a1p, b0);
            ffma2(acc[1][1], a1p, b1);
        }
        __syncthreads();
    }
    #pragma unroll
    for (int r = 0; r < 2; r++) {
        int row = tr * 2 + r;
        int bb = row >> 1, p = row & 1;
        int e = e0 + tc * 4;
        float4 bsv = *reinterpret_cast<const float4*>(&bias[n * DD + e]);
        float4 o;
        o.x = acc[r][0].x + bsv.x;
        o.y = acc[r][0].y + bsv.y;
        o.z = acc[r][1].x + bsv.z;
        o.w = acc[r][1].y + bsv.w;
        *reinterpret_cast<float4*>(&g_ys[((size_t)bb * NP + n * 2 + p) * DD + e]) = o;
    }
}

// K7: y[tok][d] = rsinv[tok] * sum_np E[tok][np] * ys[b][np][d] + x[tok][d]
// CTA tile: 128 tokens x 128 d, thread 8x8, K (np) = 128 in 4 chunks of 32.
// Grid (32 mtiles, 8 dtiles, 8 b).
__global__ __launch_bounds__(256, 2) void k_combine(const float* __restrict__ x, float* __restrict__ y) {
    __shared__ float As[128 * 32];   // [tok][np-chunk]
    __shared__ float Bs[32 * 128];   // [np][d]
    int b = blockIdx.z;
    int tok0 = b * MM + blockIdx.x * 128;
    int d0 = blockIdx.y * 128;
    int t = threadIdx.x;
    int ti = t >> 4;
    int tj = t & 15;
    float2 acc[8][4];
    #pragma unroll
    for (int r = 0; r < 8; r++)
        #pragma unroll
        for (int c = 0; c < 4; c++) acc[r][c] = make_float2(0.f, 0.f);

    for (int np0 = 0; np0 < NP; np0 += 32) {
        #pragma unroll
        for (int i = 0; i < 4; i++) {
            int idx = t + i * 256;
            int row = idx >> 3, kq = idx & 7;
            *reinterpret_cast<float4*>(&As[row * 32 + kq * 4]) =
                *reinterpret_cast<const float4*>(&g_E[(size_t)(tok0 + row) * NP + np0 + kq * 4]);
        }
        #pragma unroll
        for (int i = 0; i < 4; i++) {
            int idx = t + i * 256;
            int kk = idx >> 5, q = idx & 31;
            *reinterpret_cast<float4*>(&Bs[kk * 128 + q * 4]) =
                *reinterpret_cast<const float4*>(&g_ys[((size_t)b * NP + np0 + kk) * DD + d0 + q * 4]);
        }
        __syncthreads();
        #pragma unroll
        for (int k = 0; k < 32; k++) {
            float4 b0 = *reinterpret_cast<const float4*>(&Bs[k * 128 + tj * 8]);
            float4 b1 = *reinterpret_cast<const float4*>(&Bs[k * 128 + tj * 8 + 4]);
            float2 p0 = make_float2(b0.x, b0.y), p1 = make_float2(b0.z, b0.w);
            float2 p2 = make_float2(b1.x, b1.y), p3 = make_float2(b1.z, b1.w);
            #pragma unroll
            for (int r = 0; r < 8; r++) {
                float a = As[(ti * 8 + r) * 32 + k];
                float2 ap = make_float2(a, a);
                ffma2(acc[r][0], ap, p0);
                ffma2(acc[r][1], ap, p1);
                ffma2(acc[r][2], ap, p2);
                ffma2(acc[r][3], ap, p3);
            }
        }
        __syncthreads();
    }
    #pragma unroll
    for (int r = 0; r < 8; r++) {
        int tok = tok0 + ti * 8 + r;
        float rs = g_rsinv[tok];
        size_t idx = (size_t)tok * DD + d0 + tj * 8;
        float4 x0 = *reinterpret_cast<const float4*>(&x[idx]);
        float4 x1 = *reinterpret_cast<const float4*>(&x[idx + 4]);
        float4 o0, o1;
        o0.x = acc[r][0].x * rs + x0.x;
        o0.y = acc[r][0].y * rs + x0.y;
        o0.z = acc[r][1].x * rs + x0.z;
        o0.w = acc[r][1].y * rs + x0.w;
        o1.x = acc[r][2].x * rs + x1.x;
        o1.y = acc[r][2].y * rs + x1.y;
        o1.z = acc[r][3].x * rs + x1.z;
        o1.w = acc[r][3].y * rs + x1.w;
        *reinterpret_cast<float4*>(&y[idx]) = o0;
        *reinterpret_cast<float4*>(&y[idx + 4]) = o1;
    }
}

// ---------------------------------------------------------------------------
extern "C" void kernel_launch(void* const* d_in, const int* in_sizes, int n_in,
                              void* d_out, int out_size) {
    const float* x     = (const float*)d_in[0];  // [8,4096,1024]
    const float* phi   = (const float*)d_in[1];  // [1024,64,2]
    const float* scale = (const float*)d_in[2];  // [1]
    const float* W     = (const float*)d_in[3];  // [64,1024,1024]
    const float* bias  = (const float*)d_in[4];  // [64,1024]
    float* y = (float*)d_out;                    // [8,4096,1024]

    k_phinorm<<<NP, 256>>>(phi, scale);
    k_rinv<<<BM / 8, 256>>>(x);
    k_logits<<<BM / 128, 256>>>(x);
    k_colsum_part<<<dim3(BB, 64), 128>>>();
    k_colsum<<<BB, NP>>>();
    k_rowsum<<<BM / 8, 256>>>();
    k_xs<<<dim3(8, BB, 4), 256>>>(x);
    k_xs_reduce<<<BB * NP, 256>>>();
    k_ys<<<dim3(8, NEXP), 256>>>(W, bias);
    k_combine<<<dim3(32, 8, BB), 256>>>(x, y);
}

// round 5
// speedup vs baseline: 2.4470x; 1.7176x over previous
#include <cuda_runtime.h>
#include <cuda_bf16.h>
#include <math.h>
#include <stdint.h>

// Problem constants
#define BB 8
#define MM 4096
#define DD 1024
#define NEXP 64
#define NP 128            // NEXP * PP
#define BM (BB * MM)      // 32768 tokens
#define LOG2E 1.4426950408889634f

static __device__ __constant__ float c_eps = 1e-12f;

// ---- scratch (device globals; no allocation allowed) ----
__device__ __align__(16) __nv_bfloat16 g_phinth[NP * DD];   // phin^T hi [np][d]
__device__ __align__(16) __nv_bfloat16 g_phintl[NP * DD];   // phin^T lo [np][d]
__device__ __align__(16) __nv_bfloat16 g_xh[(size_t)BM * DD];   // x hi [tok][d]
__device__ __align__(16) __nv_bfloat16 g_xl[(size_t)BM * DD];   // x lo
__device__ __align__(16) __nv_bfloat16 g_Eh[(size_t)BM * NP];   // E hi [tok][np]
__device__ __align__(16) __nv_bfloat16 g_El[(size_t)BM * NP];   // E lo
__device__ __align__(16) __nv_bfloat16 g_ysh[BB * NP * DD];     // ys hi [b*NP+np][d]
__device__ __align__(16) __nv_bfloat16 g_ysl[BB * NP * DD];     // ys lo
__device__ float g_rinv[BM];              // per-token (1/TEMP)/max(||x||,eps)
__device__ float g_part[BB * 64 * NP];    // partial column sums
__device__ float g_colsum[BB * NP];       // dispatch softmax denominators
__device__ float g_rsinv[BM];             // 1/rowsum (combine denominators)
__device__ float g_xsp[4 * BB * NP * DD]; // partial slot inputs (4 m-segments)
__device__ float g_xs[BB * NP * DD];      // slot inputs (already /colsum)

// ============================ helpers =====================================
__device__ __forceinline__ uint32_t smem_u32(const void* p) {
    uint32_t a;
    asm("{ .reg .u64 t; cvta.to.shared.u64 t, %1; cvt.u32.u64 %0, t; }"
        : "=r"(a) : "l"(p));
    return a;
}
__device__ __forceinline__ void ldsm_x4(uint32_t& r0, uint32_t& r1, uint32_t& r2,
                                        uint32_t& r3, uint32_t a) {
    asm volatile("ldmatrix.sync.aligned.m8n8.x4.shared.b16 {%0,%1,%2,%3}, [%4];"
                 : "=r"(r0), "=r"(r1), "=r"(r2), "=r"(r3) : "r"(a));
}
__device__ __forceinline__ void ldsm_x4t(uint32_t& r0, uint32_t& r1, uint32_t& r2,
                                         uint32_t& r3, uint32_t a) {
    asm volatile("ldmatrix.sync.aligned.m8n8.x4.trans.shared.b16 {%0,%1,%2,%3}, [%4];"
                 : "=r"(r0), "=r"(r1), "=r"(r2), "=r"(r3) : "r"(a));
}
__device__ __forceinline__ void mma_bf16(float* d, const uint32_t* a, const uint32_t* b) {
    asm volatile(
        "mma.sync.aligned.m16n8k16.row.col.f32.bf16.bf16.f32 "
        "{%0,%1,%2,%3}, {%4,%5,%6,%7}, {%8,%9}, {%0,%1,%2,%3};"
        : "+f"(d[0]), "+f"(d[1]), "+f"(d[2]), "+f"(d[3])
        : "r"(a[0]), "r"(a[1]), "r"(a[2]), "r"(a[3]), "r"(b[0]), "r"(b[1]));
}
__device__ __forceinline__ void split1(float v, __nv_bfloat16& h, __nv_bfloat16& l) {
    h = __float2bfloat16_rn(v);
    l = __float2bfloat16_rn(v - __bfloat162float(h));
}
__device__ __forceinline__ void ffma2(float2& d, const float2 a, const float2 b) {
    asm("fma.rn.f32x2 %0, %1, %2, %0;"
        : "+l"(reinterpret_cast<unsigned long long&>(const_cast<float2&>(d)))
        : "l"(reinterpret_cast<const unsigned long long&>(a)),
          "l"(reinterpret_cast<const unsigned long long&>(b)));
}
__device__ __forceinline__ float ex2f(float x) {
    float r;
    asm("ex2.approx.f32 %0, %1;" : "=f"(r) : "f"(x));
    return r;
}
__device__ __forceinline__ float warpReduceSum(float v) {
    v += __shfl_down_sync(0xffffffffu, v, 16);
    v += __shfl_down_sync(0xffffffffu, v, 8);
    v += __shfl_down_sync(0xffffffffu, v, 4);
    v += __shfl_down_sync(0xffffffffu, v, 2);
    v += __shfl_down_sync(0xffffffffu, v, 1);
    return v;
}

// ===========================================================================
// K1: phin^T hi/lo
__global__ void k_phinorm(const float* __restrict__ phi, const float* __restrict__ scale) {
    int np = blockIdx.x;
    int t = threadIdx.x;
    float s = 0.f;
    for (int d = t; d < DD; d += 256) {
        float v = phi[d * NP + np];
        s += v * v;
    }
    __shared__ float red[8];
    s = warpReduceSum(s);
    if ((t & 31) == 0) red[t >> 5] = s;
    __syncthreads();
    if (t < 32) {
        float v = (t < 8) ? red[t] : 0.f;
        v = warpReduceSum(v);
        if (t == 0) red[0] = scale[0] / fmaxf(sqrtf(v), c_eps);
    }
    __syncthreads();
    float rn = red[0];
    for (int d = t; d < DD; d += 256) {
        float v = phi[d * NP + np] * rn;
        __nv_bfloat16 h, l;
        split1(v, h, l);
        g_phinth[np * DD + d] = h;
        g_phintl[np * DD + d] = l;
    }
}

// K2: row norms + x -> bf16 hi/lo. Warp per token.
__global__ void k_rinv(const float* __restrict__ x) {
    int w = threadIdx.x >> 5;
    int lane = threadIdx.x & 31;
    int tok = blockIdx.x * 8 + w;
    const float4* xr = reinterpret_cast<const float4*>(x + (size_t)tok * DD);
    float s = 0.f;
    #pragma unroll
    for (int i = 0; i < 8; i++) {
        float4 v = xr[lane + i * 32];
        s += v.x * v.x + v.y * v.y + v.z * v.z + v.w * v.w;
        __nv_bfloat16 h0, l0, h1, l1, h2, l2, h3, l3;
        split1(v.x, h0, l0); split1(v.y, h1, l1);
        split1(v.z, h2, l2); split1(v.w, h3, l3);
        size_t off = (size_t)tok * DD + (lane + i * 32) * 4;
        *reinterpret_cast<__nv_bfloat162*>(&g_xh[off])     = __halves2bfloat162(h0, h1);
        *reinterpret_cast<__nv_bfloat162*>(&g_xh[off + 2]) = __halves2bfloat162(h2, h3);
        *reinterpret_cast<__nv_bfloat162*>(&g_xl[off])     = __halves2bfloat162(l0, l1);
        *reinterpret_cast<__nv_bfloat162*>(&g_xl[off + 2]) = __halves2bfloat162(l2, l3);
    }
    s = warpReduceSum(s);
    if (lane == 0) g_rinv[tok] = 10.0f / fmaxf(sqrtf(s), c_eps);  // 1/TEMP
}

// ===========================================================================
// K3 (mma): E[tok][np] = exp2( (x . phin_col) * rinv * log2e ), bf16 hi/lo out.
// CTA 128m x 128n; warps 2m x 4n, warp tile 64x32; K=1024 in 16 chunks of 64.
#define LDA 72
__global__ __launch_bounds__(256) void k_logits_mma() {
    extern __shared__ __nv_bfloat16 sm_l[];
    __nv_bfloat16* sAh = sm_l;
    __nv_bfloat16* sAl = sAh + 128 * LDA;
    __nv_bfloat16* sBh = sAl + 128 * LDA;
    __nv_bfloat16* sBl = sBh + 128 * LDA;
    int t = threadIdx.x, lane = t & 31, wid = t >> 5;
    int tok0 = blockIdx.x * 128;
    int wm = wid & 1, wn = wid >> 1;
    float acc[4][4][4];
    #pragma unroll
    for (int a = 0; a < 4; a++)
        #pragma unroll
        for (int n = 0; n < 4; n++)
            #pragma unroll
            for (int q = 0; q < 4; q++) acc[a][n][q] = 0.f;

    int a_row = lane & 15;
    int a_col = (lane >> 4) * 8;
    int b_row = (lane & 7) + ((lane >> 4) << 3);
    int b_col = ((lane >> 3) & 1) * 8;

    for (int c = 0; c < 16; c++) {
        #pragma unroll
        for (int i = 0; i < 4; i++) {
            int idx = t + i * 256;
            int row = idx >> 3, q = idx & 7;
            size_t ga = (size_t)(tok0 + row) * DD + c * 64 + q * 8;
            size_t gb = (size_t)row * DD + c * 64 + q * 8;
            *reinterpret_cast<uint4*>(&sAh[row * LDA + q * 8]) =
                *reinterpret_cast<const uint4*>(&g_xh[ga]);
            *reinterpret_cast<uint4*>(&sAl[row * LDA + q * 8]) =
                *reinterpret_cast<const uint4*>(&g_xl[ga]);
            *reinterpret_cast<uint4*>(&sBh[row * LDA + q * 8]) =
                *reinterpret_cast<const uint4*>(&g_phinth[gb]);
            *reinterpret_cast<uint4*>(&sBl[row * LDA + q * 8]) =
                *reinterpret_cast<const uint4*>(&g_phintl[gb]);
        }
        __syncthreads();
        #pragma unroll
        for (int ks = 0; ks < 4; ks++) {
            uint32_t ah[4][4], al[4][4], bh[4][2], bl[4][2];
            #pragma unroll
            for (int a = 0; a < 4; a++) {
                int off = (wm * 64 + a * 16 + a_row) * LDA + ks * 16 + a_col;
                ldsm_x4(ah[a][0], ah[a][1], ah[a][2], ah[a][3], smem_u32(&sAh[off]));
                ldsm_x4(al[a][0], al[a][1], al[a][2], al[a][3], smem_u32(&sAl[off]));
            }
            #pragma unroll
            for (int p = 0; p < 2; p++) {
                int off = (wn * 32 + p * 16 + b_row) * LDA + ks * 16 + b_col;
                uint32_t r0, r1, r2, r3;
                ldsm_x4(r0, r1, r2, r3, smem_u32(&sBh[off]));
                bh[p * 2][0] = r0; bh[p * 2][1] = r1;
                bh[p * 2 + 1][0] = r2; bh[p * 2 + 1][1] = r3;
                ldsm_x4(r0, r1, r2, r3, smem_u32(&sBl[off]));
                bl[p * 2][0] = r0; bl[p * 2][1] = r1;
                bl[p * 2 + 1][0] = r2; bl[p * 2 + 1][1] = r3;
            }
            #pragma unroll
            for (int a = 0; a < 4; a++)
                #pragma unroll
                for (int n = 0; n < 4; n++) {
                    mma_bf16(acc[a][n], ah[a], bh[n]);
                    mma_bf16(acc[a][n], ah[a], bl[n]);
                    mma_bf16(acc[a][n], al[a], bh[n]);
                }
        }
        __syncthreads();
    }
    // epilogue: exp2, split to bf16 hi/lo
    int r0 = lane >> 2, c0 = (lane & 3) * 2;
    #pragma unroll
    for (int a = 0; a < 4; a++) {
        int row = tok0 + wm * 64 + a * 16 + r0;
        float rv0 = g_rinv[row] * LOG2E;
        float rv1 = g_rinv[row + 8] * LOG2E;
        #pragma unroll
        for (int n = 0; n < 4; n++) {
            int col = wn * 32 + n * 8 + c0;
            float e0 = ex2f(acc[a][n][0] * rv0), e1 = ex2f(acc[a][n][1] * rv0);
            float e2 = ex2f(acc[a][n][2] * rv1), e3 = ex2f(acc[a][n][3] * rv1);
            __nv_bfloat16 h0, l0, h1, l1, h2, l2, h3, l3;
            split1(e0, h0, l0); split1(e1, h1, l1);
            split1(e2, h2, l2); split1(e3, h3, l3);
            *reinterpret_cast<__nv_bfloat162*>(&g_Eh[(size_t)row * NP + col]) =
                __halves2bfloat162(h0, h1);
            *reinterpret_cast<__nv_bfloat162*>(&g_El[(size_t)row * NP + col]) =
                __halves2bfloat162(l0, l1);
            *reinterpret_cast<__nv_bfloat162*>(&g_Eh[(size_t)(row + 8) * NP + col]) =
                __halves2bfloat162(h2, h3);
            *reinterpret_cast<__nv_bfloat162*>(&g_El[(size_t)(row + 8) * NP + col]) =
                __halves2bfloat162(l2, l3);
        }
    }
}

// K4a/K4b: deterministic column sums of (Eh+El)
__global__ void k_colsum_part() {
    int b = blockIdx.x, mb = blockIdx.y;
    int np = threadIdx.x;
    int base = b * MM + mb * 64;
    float s = 0.f;
    #pragma unroll 4
    for (int i = 0; i < 64; i++) {
        size_t o = (size_t)(base + i) * NP + np;
        s += __bfloat162float(g_Eh[o]) + __bfloat162float(g_El[o]);
    }
    g_part[(b * 64 + mb) * NP + np] = s;
}
__global__ void k_colsum() {
    int b = blockIdx.x;
    int np = threadIdx.x;
    float s = 0.f;
    #pragma unroll
    for (int i = 0; i < 64; i++)
        s += g_part[(b * 64 + i) * NP + np];
    g_colsum[b * NP + np] = s;
}

// K4c: 1/rowsum per token. Warp per token.
__global__ void k_rowsum() {
    int w = threadIdx.x >> 5;
    int lane = threadIdx.x & 31;
    int tok = blockIdx.x * 8 + w;
    size_t o = (size_t)tok * NP + lane * 4;
    __nv_bfloat162 h0 = *reinterpret_cast<const __nv_bfloat162*>(&g_Eh[o]);
    __nv_bfloat162 h1 = *reinterpret_cast<const __nv_bfloat162*>(&g_Eh[o + 2]);
    __nv_bfloat162 l0 = *reinterpret_cast<const __nv_bfloat162*>(&g_El[o]);
    __nv_bfloat162 l1 = *reinterpret_cast<const __nv_bfloat162*>(&g_El[o + 2]);
    float s = __bfloat162float(h0.x) + __bfloat162float(h0.y)
            + __bfloat162float(h1.x) + __bfloat162float(h1.y)
            + __bfloat162float(l0.x) + __bfloat162float(l0.y)
            + __bfloat162float(l1.x) + __bfloat162float(l1.y);
    s = warpReduceSum(s);
    if (lane == 0) g_rsinv[tok] = 1.0f / s;
}

// ===========================================================================
// K5 (mma): xsp[seg][b][np][d] = sum_{m in seg} E[m][np] * x[m][d]
// A = E^T (trans ldmatrix), B = x (trans ldmatrix). CTA 128np x 128d.
#define LDE 136
__global__ __launch_bounds__(256) void k_xs_mma() {
    extern __shared__ __nv_bfloat16 sm_x[];
    __nv_bfloat16* sEh = sm_x;
    __nv_bfloat16* sEl = sEh + 64 * LDE;
    __nv_bfloat16* sXh = sEl + 64 * LDE;
    __nv_bfloat16* sXl = sXh + 64 * LDE;
    int t = threadIdx.x, lane = t & 31, wid = t >> 5;
    int d0 = blockIdx.x * 128;
    int b = blockIdx.y;
    int seg = blockIdx.z;
    int base = b * MM + seg * 1024;
    int wm = wid & 1, wn = wid >> 1;
    float acc[4][4][4];
    #pragma unroll
    for (int a = 0; a < 4; a++)
        #pragma unroll
        for (int n = 0; n < 4; n++)
            #pragma unroll
            for (int q = 0; q < 4; q++) acc[a][n][q] = 0.f;

    // A (trans): col = npbase + ((lane>>3)&1)*8, krow = ks*16 + (lane&7) + (lane>>4)*8
    int aA_col = ((lane >> 3) & 1) * 8;
    int aA_row = (lane & 7) + (lane >> 4) * 8;
    // B (trans): krow = ks*16 + (lane&7) + ((lane>>3)&1)*8, col = nb + (lane>>4)*8
    int aB_row = (lane & 7) + ((lane >> 3) & 1) * 8;
    int aB_col = (lane >> 4) * 8;

    for (int c = 0; c < 16; c++) {
        #pragma unroll
        for (int i = 0; i < 4; i++) {
            int idx = t + i * 256;
            int row = idx >> 4, q = idx & 15;   // 64 rows x 16 groups of 8
            size_t ge = (size_t)(base + c * 64 + row) * NP + q * 8;
            size_t gx = (size_t)(base + c * 64 + row) * DD + d0 + q * 8;
            *reinterpret_cast<uint4*>(&sEh[row * LDE + q * 8]) =
                *reinterpret_cast<const uint4*>(&g_Eh[ge]);
            *reinterpret_cast<uint4*>(&sEl[row * LDE + q * 8]) =
                *reinterpret_cast<const uint4*>(&g_El[ge]);
            *reinterpret_cast<uint4*>(&sXh[row * LDE + q * 8]) =
                *reinterpret_cast<const uint4*>(&g_xh[gx]);
            *reinterpret_cast<uint4*>(&sXl[row * LDE + q * 8]) =
                *reinterpret_cast<const uint4*>(&g_xl[gx]);
        }
        __syncthreads();
        #pragma unroll
        for (int ks = 0; ks < 4; ks++) {
            uint32_t ah[4][4], al[4][4], bh[4][2], bl[4][2];
            #pragma unroll
            for (int a = 0; a < 4; a++) {
                int npb = wm * 64 + a * 16 + aA_col;
                int off = (ks * 16 + aA_row) * LDE + npb;
                ldsm_x4t(ah[a][0], ah[a][1], ah[a][2], ah[a][3], smem_u32(&sEh[off]));
                ldsm_x4t(al[a][0], al[a][1], al[a][2], al[a][3], smem_u32(&sEl[off]));
            }
            #pragma unroll
            for (int p = 0; p < 2; p++) {
                int nb = wn * 32 + p * 16 + aB_col;
                int off = (ks * 16 + aB_row) * LDE + nb;
                uint32_t r0, r1, r2, r3;
                ldsm_x4t(r0, r1, r2, r3, smem_u32(&sXh[off]));
                bh[p * 2][0] = r0; bh[p * 2][1] = r1;
                bh[p * 2 + 1][0] = r2; bh[p * 2 + 1][1] = r3;
                ldsm_x4t(r0, r1, r2, r3, smem_u32(&sXl[off]));
                bl[p * 2][0] = r0; bl[p * 2][1] = r1;
                bl[p * 2 + 1][0] = r2; bl[p * 2 + 1][1] = r3;
            }
            #pragma unroll
            for (int a = 0; a < 4; a++)
                #pragma unroll
                for (int n = 0; n < 4; n++) {
                    mma_bf16(acc[a][n], ah[a], bh[n]);
                    mma_bf16(acc[a][n], ah[a], bl[n]);
                    mma_bf16(acc[a][n], al[a], bh[n]);
                }
        }
        __syncthreads();
    }
    int r0 = lane >> 2, c0 = (lane & 3) * 2;
    #pragma unroll
    for (int a = 0; a < 4; a++) {
        int np = wm * 64 + a * 16 + r0;
        #pragma unroll
        for (int n = 0; n < 4; n++) {
            int d = d0 + wn * 32 + n * 8 + c0;
            float* dst0 = &g_xsp[(((size_t)seg * BB + b) * NP + np) * DD + d];
            float* dst1 = &g_xsp[(((size_t)seg * BB + b) * NP + np + 8) * DD + d];
            *reinterpret_cast<float2*>(dst0) = make_float2(acc[a][n][0], acc[a][n][1]);
            *reinterpret_cast<float2*>(dst1) = make_float2(acc[a][n][2], acc[a][n][3]);
        }
    }
}

// K5b: xs = (sum_s xsp) / colsum  (fp32)
__global__ void k_xs_reduce() {
    int row = blockIdx.x;          // b*NP + np
    int b = row >> 7, np = row & 127;
    int t = threadIdx.x;
    float inv = 1.0f / g_colsum[b * NP + np];
    size_t off = ((size_t)b * NP + np) * DD + t * 4;
    float4 s = *reinterpret_cast<const float4*>(&g_xsp[off]);
    #pragma unroll
    for (int seg = 1; seg < 4; seg++) {
        float4 v = *reinterpret_cast<const float4*>(&g_xsp[(size_t)seg * BB * NP * DD + off]);
        s.x += v.x; s.y += v.y; s.z += v.z; s.w += v.w;
    }
    s.x *= inv; s.y *= inv; s.z *= inv; s.w *= inv;
    *reinterpret_cast<float4*>(&g_xs[off]) = s;
}

// K6 (SIMT fp32): ys = xs @ W[n] + b[n]; emit bf16 hi/lo
__global__ __launch_bounds__(256) void k_ys(const float* __restrict__ W, const float* __restrict__ bias) {
    __shared__ float As[16 * 32];
    __shared__ float Ws[32 * 128];
    int n = blockIdx.y;
    int e0 = blockIdx.x * 128;
    int t = threadIdx.x;
    int tr = t >> 5;
    int tc = t & 31;
    float2 acc[2][2];
    #pragma unroll
    for (int r = 0; r < 2; r++) {
        acc[r][0] = make_float2(0.f, 0.f);
        acc[r][1] = make_float2(0.f, 0.f);
    }
    for (int k0 = 0; k0 < DD; k0 += 32) {
        #pragma unroll
        for (int i = 0; i < 2; i++) {
            int lin = t + i * 256;
            int row = lin >> 5, c = lin & 31;
            int bb = row >> 1, p = row & 1;
            As[lin] = g_xs[((size_t)bb * NP + n * 2 + p) * DD + k0 + c];
        }
        #pragma unroll
        for (int i = 0; i < 16; i++) {
            int lin = t + i * 256;
            int kk = lin >> 7, e = lin & 127;
            Ws[lin] = W[((size_t)n * DD + k0 + kk) * DD + e0 + e];
        }
        __syncthreads();
        #pragma unroll
        for (int k = 0; k < 32; k++) {
            float4 bv = *reinterpret_cast<const float4*>(&Ws[k * 128 + tc * 4]);
            float2 b0 = make_float2(bv.x, bv.y);
            float2 b1 = make_float2(bv.z, bv.w);
            float a0 = As[(tr * 2 + 0) * 32 + k];
            float a1 = As[(tr * 2 + 1) * 32 + k];
            float2 a0p = make_float2(a0, a0);
            float2 a1p = make_float2(a1, a1);
            ffma2(acc[0][0], a0p, b0);
            ffma2(acc[0][1], a0p, b1);
            ffma2(acc[1][0], a1p, b0);
            ffma2(acc[1][1], a1p, b1);
        }
        __syncthreads();
    }
    #pragma unroll
    for (int r = 0; r < 2; r++) {
        int row = tr * 2 + r;
        int bb = row >> 1, p = row & 1;
        int e = e0 + tc * 4;
        float4 bsv = *reinterpret_cast<const float4*>(&bias[n * DD + e]);
        float v0 = acc[r][0].x + bsv.x;
        float v1 = acc[r][0].y + bsv.y;
        float v2 = acc[r][1].x + bsv.z;
        float v3 = acc[r][1].y + bsv.w;
        __nv_bfloat16 h0, l0, h1, l1, h2, l2, h3, l3;
        split1(v0, h0, l0); split1(v1, h1, l1);
        split1(v2, h2, l2); split1(v3, h3, l3);
        size_t o = ((size_t)bb * NP + n * 2 + p) * DD + e;
        *reinterpret_cast<__nv_bfloat162*>(&g_ysh[o])     = __halves2bfloat162(h0, h1);
        *reinterpret_cast<__nv_bfloat162*>(&g_ysh[o + 2]) = __halves2bfloat162(h2, h3);
        *reinterpret_cast<__nv_bfloat162*>(&g_ysl[o])     = __halves2bfloat162(l0, l1);
        *reinterpret_cast<__nv_bfloat162*>(&g_ysl[o + 2]) = __halves2bfloat162(l2, l3);
    }
}

// ===========================================================================
// K7 (mma): y[m][d] = rsinv[m] * sum_np E[m][np]*ys[np][d] + x[m][d]
// A = E (non-trans), B = ys (trans). CTA 128m x 128d, K=128 in 2 chunks of 64.
__global__ __launch_bounds__(256) void k_combine_mma(const float* __restrict__ x,
                                                     float* __restrict__ y) {
    extern __shared__ __nv_bfloat16 sm_c[];
    __nv_bfloat16* sAh = sm_c;                       // [128 m][72]
    __nv_bfloat16* sAl = sAh + 128 * LDA;
    __nv_bfloat16* sBh = sAl + 128 * LDA;            // [64 np][136]
    __nv_bfloat16* sBl = sBh + 64 * LDE;
    int t = threadIdx.x, lane = t & 31, wid = t >> 5;
    int b = blockIdx.z;
    int tokbase = b * MM + blockIdx.x * 128;
    int d0 = blockIdx.y * 128;
    int wm = wid & 1, wn = wid >> 1;
    float acc[4][4][4];
    #pragma unroll
    for (int a = 0; a < 4; a++)
        #pragma unroll
        for (int n = 0; n < 4; n++)
            #pragma unroll
            for (int q = 0; q < 4; q++) acc[a][n][q] = 0.f;

    int a_row = lane & 15;
    int a_col = (lane >> 4) * 8;
    int aB_row = (lane & 7) + ((lane >> 3) & 1) * 8;
    int aB_col = (lane >> 4) * 8;

    for (int c = 0; c < 2; c++) {
        #pragma unroll
        for (int i = 0; i < 4; i++) {
            int idx = t + i * 256;
            int row = idx >> 3, q = idx & 7;     // A: 128 rows x 8 groups
            size_t ge = (size_t)(tokbase + row) * NP + c * 64 + q * 8;
            *reinterpret_cast<uint4*>(&sAh[row * LDA + q * 8]) =
                *reinterpret_cast<const uint4*>(&g_Eh[ge]);
            *reinterpret_cast<uint4*>(&sAl[row * LDA + q * 8]) =
                *reinterpret_cast<const uint4*>(&g_El[ge]);
            int rowb = idx >> 4, qb = idx & 15;  // B: 64 rows x 16 groups
            size_t gy = ((size_t)b * NP + c * 64 + rowb) * DD + d0 + qb * 8;
            *reinterpret_cast<uint4*>(&sBh[rowb * LDE + qb * 8]) =
                *reinterpret_cast<const uint4*>(&g_ysh[gy]);
            *reinterpret_cast<uint4*>(&sBl[rowb * LDE + qb * 8]) =
                *reinterpret_cast<const uint4*>(&g_ysl[gy]);
        }
        __syncthreads();
        #pragma unroll
        for (int ks = 0; ks < 4; ks++) {
            uint32_t ah[4][4], al[4][4], bh[4][2], bl[4][2];
            #pragma unroll
            for (int a = 0; a < 4; a++) {
                int off = (wm * 64 + a * 16 + a_row) * LDA + ks * 16 + a_col;
                ldsm_x4(ah[a][0], ah[a][1], ah[a][2], ah[a][3], smem_u32(&sAh[off]));
                ldsm_x4(al[a][0], al[a][1], al[a][2], al[a][3], smem_u32(&sAl[off]));
            }
            #pragma unroll
            for (int p = 0; p < 2; p++) {
                int nb = wn * 32 + p * 16 + aB_col;
                int off = (ks * 16 + aB_row) * LDE + nb;
                uint32_t r0, r1, r2, r3;
                ldsm_x4t(r0, r1, r2, r3, smem_u32(&sBh[off]));
                bh[p * 2][0] = r0; bh[p * 2][1] = r1;
                bh[p * 2 + 1][0] = r2; bh[p * 2 + 1][1] = r3;
                ldsm_x4t(r0, r1, r2, r3, smem_u32(&sBl[off]));
                bl[p * 2][0] = r0; bl[p * 2][1] = r1;
                bl[p * 2 + 1][0] = r2; bl[p * 2 + 1][1] = r3;
            }
            #pragma unroll
            for (int a = 0; a < 4; a++)
                #pragma unroll
                for (int n = 0; n < 4; n++) {
                    mma_bf16(acc[a][n], ah[a], bh[n]);
                    mma_bf16(acc[a][n], ah[a], bl[n]);
                    mma_bf16(acc[a][n], al[a], bh[n]);
                }
        }
        __syncthreads();
    }
    int r0 = lane >> 2, c0 = (lane & 3) * 2;
    #pragma unroll
    for (int a = 0; a < 4; a++) {
        int m0 = tokbase + wm * 64 + a * 16 + r0;
        float rs0 = g_rsinv[m0];
        float rs1 = g_rsinv[m0 + 8];
        #pragma unroll
        for (int n = 0; n < 4; n++) {
            int d = d0 + wn * 32 + n * 8 + c0;
            size_t i0 = (size_t)m0 * DD + d;
            size_t i1 = (size_t)(m0 + 8) * DD + d;
            float2 xv0 = *reinterpret_cast<const float2*>(&x[i0]);
            float2 xv1 = *reinterpret_cast<const float2*>(&x[i1]);
            *reinterpret_cast<float2*>(&y[i0]) =
                make_float2(acc[a][n][0] * rs0 + xv0.x, acc[a][n][1] * rs0 + xv0.y);
            *reinterpret_cast<float2*>(&y[i1]) =
                make_float2(acc[a][n][2] * rs1 + xv1.x, acc[a][n][3] * rs1 + xv1.y);
        }
    }
}

// ---------------------------------------------------------------------------
extern "C" void kernel_launch(void* const* d_in, const int* in_sizes, int n_in,
                              void* d_out, int out_size) {
    const float* x     = (const float*)d_in[0];  // [8,4096,1024]
    const float* phi   = (const float*)d_in[1];  // [1024,64,2]
    const float* scale = (const float*)d_in[2];  // [1]
    const float* W     = (const float*)d_in[3];  // [64,1024,1024]
    const float* bias  = (const float*)d_in[4];  // [64,1024]
    float* y = (float*)d_out;                    // [8,4096,1024]

    const int smem_logits  = 4 * 128 * LDA * 2;                 // 73728
    const int smem_xs      = 4 * 64 * LDE * 2;                  // 69632
    const int smem_combine = 2 * 128 * LDA * 2 + 2 * 64 * LDE * 2;  // 71680
    cudaFuncSetAttribute(k_logits_mma, cudaFuncAttributeMaxDynamicSharedMemorySize, smem_logits);
    cudaFuncSetAttribute(k_xs_mma, cudaFuncAttributeMaxDynamicSharedMemorySize, smem_xs);
    cudaFuncSetAttribute(k_combine_mma, cudaFuncAttributeMaxDynamicSharedMemorySize, smem_combine);

    k_phinorm<<<NP, 256>>>(phi, scale);
    k_rinv<<<BM / 8, 256>>>(x);
    k_logits_mma<<<BM / 128, 256, smem_logits>>>();
    k_colsum_part<<<dim3(BB, 64), 128>>>();
    k_colsum<<<BB, NP>>>();
    k_rowsum<<<BM / 8, 256>>>();
    k_xs_mma<<<dim3(8, BB, 4), 256, smem_xs>>>();
    k_xs_reduce<<<BB * NP, 256>>>();
    k_ys<<<dim3(8, NEXP), 256>>>(W, bias);
    k_combine_mma<<<dim3(32, 8, BB), 256, smem_combine>>>(x, y);
}

// round 6
// speedup vs baseline: 2.6181x; 1.0699x over previous
#include <cuda_runtime.h>
#include <cuda_bf16.h>
#include <math.h>
#include <stdint.h>

// Problem constants
#define BB 8
#define MM 4096
#define DD 1024
#define NEXP 64
#define NP 128            // NEXP * PP
#define BM (BB * MM)      // 32768 tokens
#define LOG2E 1.4426950408889634f

static __device__ __constant__ float c_eps = 1e-12f;

// ---- scratch (device globals; no allocation allowed) ----
__device__ __align__(16) __nv_bfloat16 g_phinth[NP * DD];   // phin^T hi [np][d]
__device__ __align__(16) __nv_bfloat16 g_phintl[NP * DD];   // phin^T lo [np][d]
__device__ __align__(16) __nv_bfloat16 g_xh[(size_t)BM * DD];   // x hi [tok][d]
__device__ __align__(16) __nv_bfloat16 g_xl[(size_t)BM * DD];   // x lo
__device__ __align__(16) __nv_bfloat16 g_Eh[(size_t)BM * NP];   // E hi [tok][np]
__device__ __align__(16) __nv_bfloat16 g_El[(size_t)BM * NP];   // E lo
__device__ __align__(16) __nv_bfloat16 g_ysh[BB * NP * DD];     // ys hi [b*NP+np][d]
__device__ __align__(16) __nv_bfloat16 g_ysl[BB * NP * DD];     // ys lo
__device__ float g_rinv[BM];              // per-token (1/TEMP)/max(||x||,eps)
__device__ float g_part[256 * NP];        // per-mtile column partial sums
__device__ float g_colsum[BB * NP];       // dispatch softmax denominators
__device__ float g_rsinv[BM];             // 1/rowsum (combine denominators)
__device__ float g_xsp[4 * BB * NP * DD]; // partial slot inputs (4 m-segments)
__device__ float g_xs[BB * NP * DD];      // slot inputs (already /colsum)

// ============================ helpers =====================================
__device__ __forceinline__ uint32_t smem_u32(const void* p) {
    uint32_t a;
    asm("{ .reg .u64 t; cvta.to.shared.u64 t, %1; cvt.u32.u64 %0, t; }"
        : "=r"(a) : "l"(p));
    return a;
}
__device__ __forceinline__ void ldsm_x4(uint32_t& r0, uint32_t& r1, uint32_t& r2,
                                        uint32_t& r3, uint32_t a) {
    asm volatile("ldmatrix.sync.aligned.m8n8.x4.shared.b16 {%0,%1,%2,%3}, [%4];"
                 : "=r"(r0), "=r"(r1), "=r"(r2), "=r"(r3) : "r"(a));
}
__device__ __forceinline__ void ldsm_x4t(uint32_t& r0, uint32_t& r1, uint32_t& r2,
                                         uint32_t& r3, uint32_t a) {
    asm volatile("ldmatrix.sync.aligned.m8n8.x4.trans.shared.b16 {%0,%1,%2,%3}, [%4];"
                 : "=r"(r0), "=r"(r1), "=r"(r2), "=r"(r3) : "r"(a));
}
__device__ __forceinline__ void mma_bf16(float* d, const uint32_t* a, const uint32_t* b) {
    asm volatile(
        "mma.sync.aligned.m16n8k16.row.col.f32.bf16.bf16.f32 "
        "{%0,%1,%2,%3}, {%4,%5,%6,%7}, {%8,%9}, {%0,%1,%2,%3};"
        : "+f"(d[0]), "+f"(d[1]), "+f"(d[2]), "+f"(d[3])
        : "r"(a[0]), "r"(a[1]), "r"(a[2]), "r"(a[3]), "r"(b[0]), "r"(b[1]));
}
__device__ __forceinline__ void split1(float v, __nv_bfloat16& h, __nv_bfloat16& l) {
    h = __float2bfloat16_rn(v);
    l = __float2bfloat16_rn(v - __bfloat162float(h));
}
__device__ __forceinline__ float ex2f(float x) {
    float r;
    asm("ex2.approx.f32 %0, %1;" : "=f"(r) : "f"(x));
    return r;
}
__device__ __forceinline__ float warpReduceSum(float v) {
    v += __shfl_down_sync(0xffffffffu, v, 16);
    v += __shfl_down_sync(0xffffffffu, v, 8);
    v += __shfl_down_sync(0xffffffffu, v, 4);
    v += __shfl_down_sync(0xffffffffu, v, 2);
    v += __shfl_down_sync(0xffffffffu, v, 1);
    return v;
}

// ===========================================================================
// K1: phin^T hi/lo
__global__ void k_phinorm(const float* __restrict__ phi, const float* __restrict__ scale) {
    int np = blockIdx.x;
    int t = threadIdx.x;
    float s = 0.f;
    for (int d = t; d < DD; d += 256) {
        float v = phi[d * NP + np];
        s += v * v;
    }
    __shared__ float red[8];
    s = warpReduceSum(s);
    if ((t & 31) == 0) red[t >> 5] = s;
    __syncthreads();
    if (t < 32) {
        float v = (t < 8) ? red[t] : 0.f;
        v = warpReduceSum(v);
        if (t == 0) red[0] = scale[0] / fmaxf(sqrtf(v), c_eps);
    }
    __syncthreads();
    float rn = red[0];
    for (int d = t; d < DD; d += 256) {
        float v = phi[d * NP + np] * rn;
        __nv_bfloat16 h, l;
        split1(v, h, l);
        g_phinth[np * DD + d] = h;
        g_phintl[np * DD + d] = l;
    }
}

// K2: row norms + x -> bf16 hi/lo. Warp per token.
__global__ void k_rinv(const float* __restrict__ x) {
    int w = threadIdx.x >> 5;
    int lane = threadIdx.x & 31;
    int tok = blockIdx.x * 8 + w;
    const float4* xr = reinterpret_cast<const float4*>(x + (size_t)tok * DD);
    float s = 0.f;
    #pragma unroll
    for (int i = 0; i < 8; i++) {
        float4 v = xr[lane + i * 32];
        s += v.x * v.x + v.y * v.y + v.z * v.z + v.w * v.w;
        __nv_bfloat16 h0, l0, h1, l1, h2, l2, h3, l3;
        split1(v.x, h0, l0); split1(v.y, h1, l1);
        split1(v.z, h2, l2); split1(v.w, h3, l3);
        size_t off = (size_t)tok * DD + (lane + i * 32) * 4;
        *reinterpret_cast<__nv_bfloat162*>(&g_xh[off])     = __halves2bfloat162(h0, h1);
        *reinterpret_cast<__nv_bfloat162*>(&g_xh[off + 2]) = __halves2bfloat162(h2, h3);
        *reinterpret_cast<__nv_bfloat162*>(&g_xl[off])     = __halves2bfloat162(l0, l1);
        *reinterpret_cast<__nv_bfloat162*>(&g_xl[off + 2]) = __halves2bfloat162(l2, l3);
    }
    s = warpReduceSum(s);
    if (lane == 0) g_rinv[tok] = 10.0f / fmaxf(sqrtf(s), c_eps);  // 1/TEMP
}

// ===========================================================================
// K3 (mma): E[tok][np] = exp2( (x . phin_col) * rinv * log2e ), bf16 hi/lo out.
// Fused: per-token rowsum -> g_rsinv; per-tile column partials -> g_part.
#define LDA 72
__global__ __launch_bounds__(256) void k_logits_mma() {
    extern __shared__ __nv_bfloat16 sm_l[];
    __nv_bfloat16* sAh = sm_l;
    __nv_bfloat16* sAl = sAh + 128 * LDA;
    __nv_bfloat16* sBh = sAl + 128 * LDA;
    __nv_bfloat16* sBl = sBh + 128 * LDA;
    int t = threadIdx.x, lane = t & 31, wid = t >> 5;
    int tok0 = blockIdx.x * 128;
    int wm = wid & 1, wn = wid >> 1;
    float acc[4][4][4];
    #pragma unroll
    for (int a = 0; a < 4; a++)
        #pragma unroll
        for (int n = 0; n < 4; n++)
            #pragma unroll
            for (int q = 0; q < 4; q++) acc[a][n][q] = 0.f;

    int a_row = lane & 15;
    int a_col = (lane >> 4) * 8;
    int b_row = (lane & 7) + ((lane >> 4) << 3);
    int b_col = ((lane >> 3) & 1) * 8;

    for (int c = 0; c < 16; c++) {
        #pragma unroll
        for (int i = 0; i < 4; i++) {
            int idx = t + i * 256;
            int row = idx >> 3, q = idx & 7;
            size_t ga = (size_t)(tok0 + row) * DD + c * 64 + q * 8;
            size_t gb = (size_t)row * DD + c * 64 + q * 8;
            *reinterpret_cast<uint4*>(&sAh[row * LDA + q * 8]) =
                *reinterpret_cast<const uint4*>(&g_xh[ga]);
            *reinterpret_cast<uint4*>(&sAl[row * LDA + q * 8]) =
                *reinterpret_cast<const uint4*>(&g_xl[ga]);
            *reinterpret_cast<uint4*>(&sBh[row * LDA + q * 8]) =
                *reinterpret_cast<const uint4*>(&g_phinth[gb]);
            *reinterpret_cast<uint4*>(&sBl[row * LDA + q * 8]) =
                *reinterpret_cast<const uint4*>(&g_phintl[gb]);
        }
        __syncthreads();
        #pragma unroll
        for (int ks = 0; ks < 4; ks++) {
            uint32_t ah[4][4], al[4][4], bh[4][2], bl[4][2];
            #pragma unroll
            for (int a = 0; a < 4; a++) {
                int off = (wm * 64 + a * 16 + a_row) * LDA + ks * 16 + a_col;
                ldsm_x4(ah[a][0], ah[a][1], ah[a][2], ah[a][3], smem_u32(&sAh[off]));
                ldsm_x4(al[a][0], al[a][1], al[a][2], al[a][3], smem_u32(&sAl[off]));
            }
            #pragma unroll
            for (int p = 0; p < 2; p++) {
                int off = (wn * 32 + p * 16 + b_row) * LDA + ks * 16 + b_col;
                uint32_t r0, r1, r2, r3;
                ldsm_x4(r0, r1, r2, r3, smem_u32(&sBh[off]));
                bh[p * 2][0] = r0; bh[p * 2][1] = r1;
                bh[p * 2 + 1][0] = r2; bh[p * 2 + 1][1] = r3;
                ldsm_x4(r0, r1, r2, r3, smem_u32(&sBl[off]));
                bl[p * 2][0] = r0; bl[p * 2][1] = r1;
                bl[p * 2 + 1][0] = r2; bl[p * 2 + 1][1] = r3;
            }
            #pragma unroll
            for (int a = 0; a < 4; a++)
                #pragma unroll
                for (int n = 0; n < 4; n++) {
                    mma_bf16(acc[a][n], ah[a], bh[n]);
                    mma_bf16(acc[a][n], ah[a], bl[n]);
                    mma_bf16(acc[a][n], al[a], bh[n]);
                }
        }
        __syncthreads();
    }
    // epilogue: exp2, split to bf16 hi/lo; accumulate row/col sums
    int r0 = lane >> 2, c0 = (lane & 3) * 2;
    float rsum[4][2];   // [a][row-half]
    float csum[4][2];   // [n][q&1]
    #pragma unroll
    for (int a = 0; a < 4; a++) { rsum[a][0] = 0.f; rsum[a][1] = 0.f; }
    #pragma unroll
    for (int n = 0; n < 4; n++) { csum[n][0] = 0.f; csum[n][1] = 0.f; }
    #pragma unroll
    for (int a = 0; a < 4; a++) {
        int row = tok0 + wm * 64 + a * 16 + r0;
        float rv0 = g_rinv[row] * LOG2E;
        float rv1 = g_rinv[row + 8] * LOG2E;
        #pragma unroll
        for (int n = 0; n < 4; n++) {
            int col = wn * 32 + n * 8 + c0;
            float e0 = ex2f(acc[a][n][0] * rv0), e1 = ex2f(acc[a][n][1] * rv0);
            float e2 = ex2f(acc[a][n][2] * rv1), e3 = ex2f(acc[a][n][3] * rv1);
            rsum[a][0] += e0 + e1;
            rsum[a][1] += e2 + e3;
            csum[n][0] += e0 + e2;
            csum[n][1] += e1 + e3;
            __nv_bfloat16 h0, l0, h1, l1, h2, l2, h3, l3;
            split1(e0, h0, l0); split1(e1, h1, l1);
            split1(e2, h2, l2); split1(e3, h3, l3);
            *reinterpret_cast<__nv_bfloat162*>(&g_Eh[(size_t)row * NP + col]) =
                __halves2bfloat162(h0, h1);
            *reinterpret_cast<__nv_bfloat162*>(&g_El[(size_t)row * NP + col]) =
                __halves2bfloat162(l0, l1);
            *reinterpret_cast<__nv_bfloat162*>(&g_Eh[(size_t)(row + 8) * NP + col]) =
                __halves2bfloat162(h2, h3);
            *reinterpret_cast<__nv_bfloat162*>(&g_El[(size_t)(row + 8) * NP + col]) =
                __halves2bfloat162(l2, l3);
        }
    }
    // reductions into smem scratch (reuse tile smem; all mma reads are done)
    float* srow = reinterpret_cast<float*>(sm_l);          // [4 wn][128 rows]
    float* scol = srow + 4 * 128;                          // [2 wm][128 cols]
    __syncthreads();
    #pragma unroll
    for (int a = 0; a < 4; a++)
        #pragma unroll
        for (int h = 0; h < 2; h++) {
            float v = rsum[a][h];
            v += __shfl_xor_sync(0xffffffffu, v, 1);
            v += __shfl_xor_sync(0xffffffffu, v, 2);
            if ((lane & 3) == 0)
                srow[wn * 128 + wm * 64 + a * 16 + h * 8 + r0] = v;
        }
    #pragma unroll
    for (int n = 0; n < 4; n++)
        #pragma unroll
        for (int q1 = 0; q1 < 2; q1++) {
            float v = csum[n][q1];
            v += __shfl_xor_sync(0xffffffffu, v, 4);
            v += __shfl_xor_sync(0xffffffffu, v, 8);
            v += __shfl_xor_sync(0xffffffffu, v, 16);
            if (lane < 4)
                scol[wm * 128 + wn * 32 + n * 8 + lane * 2 + q1] = v;
        }
    __syncthreads();
    if (t < 128) {
        float rs = srow[t] + srow[128 + t] + srow[256 + t] + srow[384 + t];
        g_rsinv[tok0 + t] = 1.0f / rs;
        g_part[blockIdx.x * NP + t] = scol[t] + scol[128 + t];
    }
}

// K4: final column sums per batch (32 m-tiles each)
__global__ void k_colsum() {
    int b = blockIdx.x;
    int np = threadIdx.x;
    float s = 0.f;
    #pragma unroll
    for (int i = 0; i < 32; i++)
        s += g_part[(b * 32 + i) * NP + np];
    g_colsum[b * NP + np] = s;
}

// ===========================================================================
// K5 (mma): xsp[seg][b][np][d] = sum_{m in seg} E[m][np] * x[m][d]
#define LDE 136
__global__ __launch_bounds__(256) void k_xs_mma() {
    extern __shared__ __nv_bfloat16 sm_x[];
    __nv_bfloat16* sEh = sm_x;
    __nv_bfloat16* sEl = sEh + 64 * LDE;
    __nv_bfloat16* sXh = sEl + 64 * LDE;
    __nv_bfloat16* sXl = sXh + 64 * LDE;
    int t = threadIdx.x, lane = t & 31, wid = t >> 5;
    int d0 = blockIdx.x * 128;
    int b = blockIdx.y;
    int seg = blockIdx.z;
    int base = b * MM + seg * 1024;
    int wm = wid & 1, wn = wid >> 1;
    float acc[4][4][4];
    #pragma unroll
    for (int a = 0; a < 4; a++)
        #pragma unroll
        for (int n = 0; n < 4; n++)
            #pragma unroll
            for (int q = 0; q < 4; q++) acc[a][n][q] = 0.f;

    int aA_col = ((lane >> 3) & 1) * 8;
    int aA_row = (lane & 7) + (lane >> 4) * 8;
    int aB_row = (lane & 7) + ((lane >> 3) & 1) * 8;
    int aB_col = (lane >> 4) * 8;

    for (int c = 0; c < 16; c++) {
        #pragma unroll
        for (int i = 0; i < 4; i++) {
            int idx = t + i * 256;
            int row = idx >> 4, q = idx & 15;
            size_t ge = (size_t)(base + c * 64 + row) * NP + q * 8;
            size_t gx = (size_t)(base + c * 64 + row) * DD + d0 + q * 8;
            *reinterpret_cast<uint4*>(&sEh[row * LDE + q * 8]) =
                *reinterpret_cast<const uint4*>(&g_Eh[ge]);
            *reinterpret_cast<uint4*>(&sEl[row * LDE + q * 8]) =
                *reinterpret_cast<const uint4*>(&g_El[ge]);
            *reinterpret_cast<uint4*>(&sXh[row * LDE + q * 8]) =
                *reinterpret_cast<const uint4*>(&g_xh[gx]);
            *reinterpret_cast<uint4*>(&sXl[row * LDE + q * 8]) =
                *reinterpret_cast<const uint4*>(&g_xl[gx]);
        }
        __syncthreads();
        #pragma unroll
        for (int ks = 0; ks < 4; ks++) {
            uint32_t ah[4][4], al[4][4], bh[4][2], bl[4][2];
            #pragma unroll
            for (int a = 0; a < 4; a++) {
                int npb = wm * 64 + a * 16 + aA_col;
                int off = (ks * 16 + aA_row) * LDE + npb;
                ldsm_x4t(ah[a][0], ah[a][1], ah[a][2], ah[a][3], smem_u32(&sEh[off]));
                ldsm_x4t(al[a][0], al[a][1], al[a][2], al[a][3], smem_u32(&sEl[off]));
            }
            #pragma unroll
            for (int p = 0; p < 2; p++) {
                int nb = wn * 32 + p * 16 + aB_col;
                int off = (ks * 16 + aB_row) * LDE + nb;
                uint32_t r0, r1, r2, r3;
                ldsm_x4t(r0, r1, r2, r3, smem_u32(&sXh[off]));
                bh[p * 2][0] = r0; bh[p * 2][1] = r1;
                bh[p * 2 + 1][0] = r2; bh[p * 2 + 1][1] = r3;
                ldsm_x4t(r0, r1, r2, r3, smem_u32(&sXl[off]));
                bl[p * 2][0] = r0; bl[p * 2][1] = r1;
                bl[p * 2 + 1][0] = r2; bl[p * 2 + 1][1] = r3;
            }
            #pragma unroll
            for (int a = 0; a < 4; a++)
                #pragma unroll
                for (int n = 0; n < 4; n++) {
                    mma_bf16(acc[a][n], ah[a], bh[n]);
                    mma_bf16(acc[a][n], ah[a], bl[n]);
                    mma_bf16(acc[a][n], al[a], bh[n]);
                }
        }
        __syncthreads();
    }
    int r0 = lane >> 2, c0 = (lane & 3) * 2;
    #pragma unroll
    for (int a = 0; a < 4; a++) {
        int np = wm * 64 + a * 16 + r0;
        #pragma unroll
        for (int n = 0; n < 4; n++) {
            int d = d0 + wn * 32 + n * 8 + c0;
            float* dst0 = &g_xsp[(((size_t)seg * BB + b) * NP + np) * DD + d];
            float* dst1 = &g_xsp[(((size_t)seg * BB + b) * NP + np + 8) * DD + d];
            *reinterpret_cast<float2*>(dst0) = make_float2(acc[a][n][0], acc[a][n][1]);
            *reinterpret_cast<float2*>(dst1) = make_float2(acc[a][n][2], acc[a][n][3]);
        }
    }
}

// K5b: xs = (sum_s xsp) / colsum  (fp32)
__global__ void k_xs_reduce() {
    int row = blockIdx.x;          // b*NP + np
    int b = row >> 7, np = row & 127;
    int t = threadIdx.x;
    float inv = 1.0f / g_colsum[b * NP + np];
    size_t off = ((size_t)b * NP + np) * DD + t * 4;
    float4 s = *reinterpret_cast<const float4*>(&g_xsp[off]);
    #pragma unroll
    for (int seg = 1; seg < 4; seg++) {
        float4 v = *reinterpret_cast<const float4*>(&g_xsp[(size_t)seg * BB * NP * DD + off]);
        s.x += v.x; s.y += v.y; s.z += v.z; s.w += v.w;
    }
    s.x *= inv; s.y *= inv; s.z *= inv; s.w *= inv;
    *reinterpret_cast<float4*>(&g_xs[off]) = s;
}

// ===========================================================================
// K6 (mma): ys[(b,p)][e] = sum_d xs[(b,p)][d] * W[n][d][e] + bias[n][e]
// M=16 rows, CTA covers N=256 e-cols of one expert; W converted in-kernel.
#define LDW 264
#define LDK 72
__global__ __launch_bounds__(256) void k_ys_mma(const float* __restrict__ W,
                                                const float* __restrict__ bias) {
    extern __shared__ __nv_bfloat16 sm_y[];
    __nv_bfloat16* sWh = sm_y;                 // [64 k][LDW]
    __nv_bfloat16* sWl = sWh + 64 * LDW;
    __nv_bfloat16* sAh = sWl + 64 * LDW;       // [16 m][LDK]
    __nv_bfloat16* sAl = sAh + 16 * LDK;
    int t = threadIdx.x, lane = t & 31, wid = t >> 5;
    int nexp = blockIdx.y;
    int e0 = blockIdx.x * 256;
    float acc[4][4];
    #pragma unroll
    for (int n = 0; n < 4; n++)
        #pragma unroll
        for (int q = 0; q < 4; q++) acc[n][q] = 0.f;

    int a_row = lane & 15;
    int a_col = (lane >> 4) * 8;
    int aB_row = (lane & 7) + ((lane >> 3) & 1) * 8;
    int aB_col = (lane >> 4) * 8;

    for (int c = 0; c < 16; c++) {
        int k0 = c * 64;
        // A: xs rows (b,p) for this expert, 16 x 64, fp32 -> hi/lo
        if (t < 128) {
            int row = t >> 3, q = t & 7;      // 16 rows x 8 groups
            int bb = row >> 1, p = row & 1;
            const float* src = &g_xs[((size_t)bb * NP + nexp * 2 + p) * DD + k0 + q * 8];
            float4 v0 = *reinterpret_cast<const float4*>(src);
            float4 v1 = *reinterpret_cast<const float4*>(src + 4);
            float v[8] = {v0.x, v0.y, v0.z, v0.w, v1.x, v1.y, v1.z, v1.w};
            uint32_t hs[8], ls[8];
            #pragma unroll
            for (int j = 0; j < 8; j++) {
                __nv_bfloat16 h, l;
                split1(v[j], h, l);
                hs[j] = (uint32_t)__bfloat16_as_ushort(h);
                ls[j] = (uint32_t)__bfloat16_as_ushort(l);
            }
            uint4 hi = {hs[0] | (hs[1] << 16), hs[2] | (hs[3] << 16),
                        hs[4] | (hs[5] << 16), hs[6] | (hs[7] << 16)};
            uint4 lo = {ls[0] | (ls[1] << 16), ls[2] | (ls[3] << 16),
                        ls[4] | (ls[5] << 16), ls[6] | (ls[7] << 16)};
            *reinterpret_cast<uint4*>(&sAh[row * LDK + q * 8]) = hi;
            *reinterpret_cast<uint4*>(&sAl[row * LDK + q * 8]) = lo;
        }
        // W: 64 k x 256 e, fp32 -> hi/lo
        #pragma unroll
        for (int i = 0; i < 8; i++) {
            int idx = t + i * 256;
            int row = idx >> 5, q = idx & 31;   // 64 rows x 32 groups of 8
            const float* src = &W[((size_t)nexp * DD + k0 + row) * DD + e0 + q * 8];
            float4 v0 = *reinterpret_cast<const float4*>(src);
            float4 v1 = *reinterpret_cast<const float4*>(src + 4);
            float v[8] = {v0.x, v0.y, v0.z, v0.w, v1.x, v1.y, v1.z, v1.w};
            uint32_t hs[8], ls[8];
            #pragma unroll
            for (int j = 0; j < 8; j++) {
                __nv_bfloat16 h, l;
                split1(v[j], h, l);
                hs[j] = (uint32_t)__bfloat16_as_ushort(h);
                ls[j] = (uint32_t)__bfloat16_as_ushort(l);
            }
            uint4 hi = {hs[0] | (hs[1] << 16), hs[2] | (hs[3] << 16),
                        hs[4] | (hs[5] << 16), hs[6] | (hs[7] << 16)};
            uint4 lo = {ls[0] | (ls[1] << 16), ls[2] | (ls[3] << 16),
                        ls[4] | (ls[5] << 16), ls[6] | (ls[7] << 16)};
            *reinterpret_cast<uint4*>(&sWh[row * LDW + q * 8]) = hi;
            *reinterpret_cast<uint4*>(&sWl[row * LDW + q * 8]) = lo;
        }
        __syncthreads();
        #pragma unroll
        for (int ks = 0; ks < 4; ks++) {
            uint32_t ah[4], al[4], bh[4][2], bl[4][2];
            {
                int off = a_row * LDK + ks * 16 + a_col;
                ldsm_x4(ah[0], ah[1], ah[2], ah[3], smem_u32(&sAh[off]));
                ldsm_x4(al[0], al[1], al[2], al[3], smem_u32(&sAl[off]));
            }
            #pragma unroll
            for (int p = 0; p < 2; p++) {
                int nb = wid * 32 + p * 16 + aB_col;
                int off = (ks * 16 + aB_row) * LDW + nb;
                uint32_t r0, r1, r2, r3;
                ldsm_x4t(r0, r1, r2, r3, smem_u32(&sWh[off]));
                bh[p * 2][0] = r0; bh[p * 2][1] = r1;
                bh[p * 2 + 1][0] = r2; bh[p * 2 + 1][1] = r3;
                ldsm_x4t(r0, r1, r2, r3, smem_u32(&sWl[off]));
                bl[p * 2][0] = r0; bl[p * 2][1] = r1;
                bl[p * 2 + 1][0] = r2; bl[p * 2 + 1][1] = r3;
            }
            #pragma unroll
            for (int n = 0; n < 4; n++) {
                mma_bf16(acc[n], ah, bh[n]);
                mma_bf16(acc[n], ah, bl[n]);
                mma_bf16(acc[n], al, bh[n]);
            }
        }
        __syncthreads();
    }
    // epilogue: + bias, split hi/lo, store
    int r0 = lane >> 2, c0 = (lane & 3) * 2;
    #pragma unroll
    for (int n = 0; n < 4; n++) {
        int e = e0 + wid * 32 + n * 8 + c0;
        float2 bv = *reinterpret_cast<const float2*>(&bias[nexp * DD + e]);
        #pragma unroll
        for (int h = 0; h < 2; h++) {
            int row = r0 + h * 8;              // (b,p)
            int bb = row >> 1, p = row & 1;
            float v0 = acc[n][h * 2 + 0] + bv.x;
            float v1 = acc[n][h * 2 + 1] + bv.y;
            __nv_bfloat16 h0, l0, h1, l1;
            split1(v0, h0, l0); split1(v1, h1, l1);
            size_t o = ((size_t)bb * NP + nexp * 2 + p) * DD + e;
            *reinterpret_cast<__nv_bfloat162*>(&g_ysh[o]) = __halves2bfloat162(h0, h1);
            *reinterpret_cast<__nv_bfloat162*>(&g_ysl[o]) = __halves2bfloat162(l0, l1);
        }
    }
}

// ===========================================================================
// K7 (mma): y[m][d] = rsinv[m] * sum_np E[m][np]*ys[np][d] + x[m][d]
__global__ __launch_bounds__(256) void k_combine_mma(const float* __restrict__ x,
                                                     float* __restrict__ y) {
    extern __shared__ __nv_bfloat16 sm_c[];
    __nv_bfloat16* sAh = sm_c;                       // [128 m][72]
    __nv_bfloat16* sAl = sAh + 128 * LDA;
    __nv_bfloat16* sBh = sAl + 128 * LDA;            // [64 np][136]
    __nv_bfloat16* sBl = sBh + 64 * LDE;
    int t = threadIdx.x, lane = t & 31, wid = t >> 5;
    int b = blockIdx.z;
    int tokbase = b * MM + blockIdx.x * 128;
    int d0 = blockIdx.y * 128;
    int wm = wid & 1, wn = wid >> 1;
    float acc[4][4][4];
    #pragma unroll
    for (int a = 0; a < 4; a++)
        #pragma unroll
        for (int n = 0; n < 4; n++)
            #pragma unroll
            for (int q = 0; q < 4; q++) acc[a][n][q] = 0.f;

    int a_row = lane & 15;
    int a_col = (lane >> 4) * 8;
    int aB_row = (lane & 7) + ((lane >> 3) & 1) * 8;
    int aB_col = (lane >> 4) * 8;

    for (int c = 0; c < 2; c++) {
        #pragma unroll
        for (int i = 0; i < 4; i++) {
            int idx = t + i * 256;
            int row = idx >> 3, q = idx & 7;
            size_t ge = (size_t)(tokbase + row) * NP + c * 64 + q * 8;
            *reinterpret_cast<uint4*>(&sAh[row * LDA + q * 8]) =
                *reinterpret_cast<const uint4*>(&g_Eh[ge]);
            *reinterpret_cast<uint4*>(&sAl[row * LDA + q * 8]) =
                *reinterpret_cast<const uint4*>(&g_El[ge]);
            int rowb = idx >> 4, qb = idx & 15;
            size_t gy = ((size_t)b * NP + c * 64 + rowb) * DD + d0 + qb * 8;
            *reinterpret_cast<uint4*>(&sBh[rowb * LDE + qb * 8]) =
                *reinterpret_cast<const uint4*>(&g_ysh[gy]);
            *reinterpret_cast<uint4*>(&sBl[rowb * LDE + qb * 8]) =
                *reinterpret_cast<const uint4*>(&g_ysl[gy]);
        }
        __syncthreads();
        #pragma unroll
        for (int ks = 0; ks < 4; ks++) {
            uint32_t ah[4][4], al[4][4], bh[4][2], bl[4][2];
            #pragma unroll
            for (int a = 0; a < 4; a++) {
                int off = (wm * 64 + a * 16 + a_row) * LDA + ks * 16 + a_col;
                ldsm_x4(ah[a][0], ah[a][1], ah[a][2], ah[a][3], smem_u32(&sAh[off]));
                ldsm_x4(al[a][0], al[a][1], al[a][2], al[a][3], smem_u32(&sAl[off]));
            }
            #pragma unroll
            for (int p = 0; p < 2; p++) {
                int nb = wn * 32 + p * 16 + aB_col;
                int off = (ks * 16 + aB_row) * LDE + nb;
                uint32_t r0, r1, r2, r3;
                ldsm_x4t(r0, r1, r2, r3, smem_u32(&sBh[off]));
                bh[p * 2][0] = r0; bh[p * 2][1] = r1;
                bh[p * 2 + 1][0] = r2; bh[p * 2 + 1][1] = r3;
                ldsm_x4t(r0, r1, r2, r3, smem_u32(&sBl[off]));
                bl[p * 2][0] = r0; bl[p * 2][1] = r1;
                bl[p * 2 + 1][0] = r2; bl[p * 2 + 1][1] = r3;
            }
            #pragma unroll
            for (int a = 0; a < 4; a++)
                #pragma unroll
                for (int n = 0; n < 4; n++) {
                    mma_bf16(acc[a][n], ah[a], bh[n]);
                    mma_bf16(acc[a][n], ah[a], bl[n]);
                    mma_bf16(acc[a][n], al[a], bh[n]);
                }
        }
        __syncthreads();
    }
    int r0 = lane >> 2, c0 = (lane & 3) * 2;
    #pragma unroll
    for (int a = 0; a < 4; a++) {
        int m0 = tokbase + wm * 64 + a * 16 + r0;
        float rs0 = g_rsinv[m0];
        float rs1 = g_rsinv[m0 + 8];
        #pragma unroll
        for (int n = 0; n < 4; n++) {
            int d = d0 + wn * 32 + n * 8 + c0;
            size_t i0 = (size_t)m0 * DD + d;
            size_t i1 = (size_t)(m0 + 8) * DD + d;
            float2 xv0 = *reinterpret_cast<const float2*>(&x[i0]);
            float2 xv1 = *reinterpret_cast<const float2*>(&x[i1]);
            *reinterpret_cast<float2*>(&y[i0]) =
                make_float2(acc[a][n][0] * rs0 + xv0.x, acc[a][n][1] * rs0 + xv0.y);
            *reinterpret_cast<float2*>(&y[i1]) =
                make_float2(acc[a][n][2] * rs1 + xv1.x, acc[a][n][3] * rs1 + xv1.y);
        }
    }
}

// ---------------------------------------------------------------------------
extern "C" void kernel_launch(void* const* d_in, const int* in_sizes, int n_in,
                              void* d_out, int out_size) {
    const float* x     = (const float*)d_in[0];  // [8,4096,1024]
    const float* phi   = (const float*)d_in[1];  // [1024,64,2]
    const float* scale = (const float*)d_in[2];  // [1]
    const float* W     = (const float*)d_in[3];  // [64,1024,1024]
    const float* bias  = (const float*)d_in[4];  // [64,1024]
    float* y = (float*)d_out;                    // [8,4096,1024]

    const int smem_logits  = 4 * 128 * LDA * 2;                     // 73728
    const int smem_xs      = 4 * 64 * LDE * 2;                      // 69632
    const int smem_ys      = 2 * 64 * LDW * 2 + 2 * 16 * LDK * 2;   // 72192
    const int smem_combine = 2 * 128 * LDA * 2 + 2 * 64 * LDE * 2;  // 71680
    cudaFuncSetAttribute(k_logits_mma, cudaFuncAttributeMaxDynamicSharedMemorySize, smem_logits);
    cudaFuncSetAttribute(k_xs_mma, cudaFuncAttributeMaxDynamicSharedMemorySize, smem_xs);
    cudaFuncSetAttribute(k_ys_mma, cudaFuncAttributeMaxDynamicSharedMemorySize, smem_ys);
    cudaFuncSetAttribute(k_combine_mma, cudaFuncAttributeMaxDynamicSharedMemorySize, smem_combine);

    k_phinorm<<<NP, 256>>>(phi, scale);
    k_rinv<<<BM / 8, 256>>>(x);
    k_logits_mma<<<BM / 128, 256, smem_logits>>>();
    k_colsum<<<BB, NP>>>();
    k_xs_mma<<<dim3(8, BB, 4), 256, smem_xs>>>();
    k_xs_reduce<<<BB * NP, 256>>>();
    k_ys_mma<<<dim3(4, NEXP), 256, smem_ys>>>(W, bias);
    k_combine_mma<<<dim3(32, 8, BB), 256, smem_combine>>>(x, y);
}

// round 7
// speedup vs baseline: 2.7687x; 1.0575x over previous
#include <cuda_runtime.h>
#include <cuda_bf16.h>
#include <math.h>
#include <stdint.h>

// Problem constants
#define BB 8
#define MM 4096
#define DD 1024
#define NEXP 64
#define NP 128            // NEXP * PP
#define BM (BB * MM)      // 32768 tokens
#define LOG2E 1.4426950408889634f

static __device__ __constant__ float c_eps = 1e-12f;

// ---- scratch (device globals; no allocation allowed) ----
__device__ __align__(16) __nv_bfloat16 g_phinth[NP * DD];   // phin^T hi [np][d]
__device__ __align__(16) __nv_bfloat16 g_phintl[NP * DD];   // phin^T lo [np][d]
__device__ __align__(16) __nv_bfloat16 g_xh[(size_t)BM * DD];   // x hi [tok][d]
__device__ __align__(16) __nv_bfloat16 g_xl[(size_t)BM * DD];   // x lo
__device__ __align__(16) __nv_bfloat16 g_Eh[(size_t)BM * NP];   // E hi [tok][np]
__device__ __align__(16) __nv_bfloat16 g_El[(size_t)BM * NP];   // E lo
__device__ __align__(16) __nv_bfloat16 g_ysh[BB * NP * DD];     // ys hi [b*NP+np][d]
__device__ __align__(16) __nv_bfloat16 g_ysl[BB * NP * DD];     // ys lo
__device__ float g_rinv[BM];              // per-token (1/TEMP)/max(||x||,eps)
__device__ float g_part[256 * NP];        // per-mtile column partial sums
__device__ float g_colsum[BB * NP];       // dispatch softmax denominators
__device__ float g_rsinv[BM];             // 1/rowsum (combine denominators)
__device__ float g_xsp[4 * BB * NP * DD]; // partial slot inputs (4 m-segments)

// ============================ helpers =====================================
__device__ __forceinline__ uint32_t smem_u32(const void* p) {
    uint32_t a;
    asm("{ .reg .u64 t; cvta.to.shared.u64 t, %1; cvt.u32.u64 %0, t; }"
        : "=r"(a) : "l"(p));
    return a;
}
__device__ __forceinline__ void cp_async16(uint32_t saddr, const void* gptr) {
    asm volatile("cp.async.ca.shared.global [%0], [%1], 16;"
                 :: "r"(saddr), "l"(gptr));
}
#define CP_COMMIT() asm volatile("cp.async.commit_group;" ::: "memory")
#define CP_WAIT1()  asm volatile("cp.async.wait_group 1;" ::: "memory")
__device__ __forceinline__ void ldsm_x4(uint32_t& r0, uint32_t& r1, uint32_t& r2,
                                        uint32_t& r3, uint32_t a) {
    asm volatile("ldmatrix.sync.aligned.m8n8.x4.shared.b16 {%0,%1,%2,%3}, [%4];"
                 : "=r"(r0), "=r"(r1), "=r"(r2), "=r"(r3) : "r"(a));
}
__device__ __forceinline__ void ldsm_x4t(uint32_t& r0, uint32_t& r1, uint32_t& r2,
                                         uint32_t& r3, uint32_t a) {
    asm volatile("ldmatrix.sync.aligned.m8n8.x4.trans.shared.b16 {%0,%1,%2,%3}, [%4];"
                 : "=r"(r0), "=r"(r1), "=r"(r2), "=r"(r3) : "r"(a));
}
__device__ __forceinline__ void mma_bf16(float* d, const uint32_t* a, const uint32_t* b) {
    asm volatile(
        "mma.sync.aligned.m16n8k16.row.col.f32.bf16.bf16.f32 "
        "{%0,%1,%2,%3}, {%4,%5,%6,%7}, {%8,%9}, {%0,%1,%2,%3};"
        : "+f"(d[0]), "+f"(d[1]), "+f"(d[2]), "+f"(d[3])
        : "r"(a[0]), "r"(a[1]), "r"(a[2]), "r"(a[3]), "r"(b[0]), "r"(b[1]));
}
__device__ __forceinline__ void split1(float v, __nv_bfloat16& h, __nv_bfloat16& l) {
    h = __float2bfloat16_rn(v);
    l = __float2bfloat16_rn(v - __bfloat162float(h));
}
__device__ __forceinline__ float ex2f(float x) {
    float r;
    asm("ex2.approx.f32 %0, %1;" : "=f"(r) : "f"(x));
    return r;
}
__device__ __forceinline__ float warpReduceSum(float v) {
    v += __shfl_down_sync(0xffffffffu, v, 16);
    v += __shfl_down_sync(0xffffffffu, v, 8);
    v += __shfl_down_sync(0xffffffffu, v, 4);
    v += __shfl_down_sync(0xffffffffu, v, 2);
    v += __shfl_down_sync(0xffffffffu, v, 1);
    return v;
}

// ===========================================================================
// K1: phin^T hi/lo
__global__ void k_phinorm(const float* __restrict__ phi, const float* __restrict__ scale) {
    int np = blockIdx.x;
    int t = threadIdx.x;
    float s = 0.f;
    for (int d = t; d < DD; d += 256) {
        float v = phi[d * NP + np];
        s += v * v;
    }
    __shared__ float red[8];
    s = warpReduceSum(s);
    if ((t & 31) == 0) red[t >> 5] = s;
    __syncthreads();
    if (t < 32) {
        float v = (t < 8) ? red[t] : 0.f;
        v = warpReduceSum(v);
        if (t == 0) red[0] = scale[0] / fmaxf(sqrtf(v), c_eps);
    }
    __syncthreads();
    float rn = red[0];
    for (int d = t; d < DD; d += 256) {
        float v = phi[d * NP + np] * rn;
        __nv_bfloat16 h, l;
        split1(v, h, l);
        g_phinth[np * DD + d] = h;
        g_phintl[np * DD + d] = l;
    }
}

// K2: row norms + x -> bf16 hi/lo. Warp per token.
__global__ void k_rinv(const float* __restrict__ x) {
    int w = threadIdx.x >> 5;
    int lane = threadIdx.x & 31;
    int tok = blockIdx.x * 8 + w;
    const float4* xr = reinterpret_cast<const float4*>(x + (size_t)tok * DD);
    float s = 0.f;
    #pragma unroll
    for (int i = 0; i < 8; i++) {
        float4 v = xr[lane + i * 32];
        s += v.x * v.x + v.y * v.y + v.z * v.z + v.w * v.w;
        __nv_bfloat16 h0, l0, h1, l1, h2, l2, h3, l3;
        split1(v.x, h0, l0); split1(v.y, h1, l1);
        split1(v.z, h2, l2); split1(v.w, h3, l3);
        size_t off = (size_t)tok * DD + (lane + i * 32) * 4;
        *reinterpret_cast<__nv_bfloat162*>(&g_xh[off])     = __halves2bfloat162(h0, h1);
        *reinterpret_cast<__nv_bfloat162*>(&g_xh[off + 2]) = __halves2bfloat162(h2, h3);
        *reinterpret_cast<__nv_bfloat162*>(&g_xl[off])     = __halves2bfloat162(l0, l1);
        *reinterpret_cast<__nv_bfloat162*>(&g_xl[off + 2]) = __halves2bfloat162(l2, l3);
    }
    s = warpReduceSum(s);
    if (lane == 0) g_rinv[tok] = 10.0f / fmaxf(sqrtf(s), c_eps);  // 1/TEMP
}

// ===========================================================================
// K3 (mma, cp.async 2-stage): E = exp2((x . phin) * rinv * log2e), hi/lo out.
// CTA 128m x 128n, K chunks of 32. Fused rowsum + column partials.
#define LDA 40
#define L_AST (128 * LDA)
#define L_SST (4 * L_AST)
__global__ __launch_bounds__(256) void k_logits_mma() {
    extern __shared__ __nv_bfloat16 sm_l[];
    int t = threadIdx.x, lane = t & 31, wid = t >> 5;
    int tok0 = blockIdx.x * 128;
    int wm = wid & 1, wn = wid >> 1;
    float acc[4][4][4];
    #pragma unroll
    for (int a = 0; a < 4; a++)
        #pragma unroll
        for (int n = 0; n < 4; n++)
            #pragma unroll
            for (int q = 0; q < 4; q++) acc[a][n][q] = 0.f;

    int a_row = lane & 15;
    int a_col = (lane >> 4) * 8;
    int b_row = (lane & 7) + ((lane >> 4) << 3);
    int b_col = ((lane >> 3) & 1) * 8;

    int l_row0 = t >> 2, l_q0 = t & 3;
    int l_row1 = (t + 256) >> 2, l_q1 = (t + 256) & 3;

    #define L_LOAD(c, s) do { \
        __nv_bfloat16* base = sm_l + (s) * L_SST; \
        int rows[2] = {l_row0, l_row1}; \
        int qs[2] = {l_q0, l_q1}; \
        _Pragma("unroll") \
        for (int i = 0; i < 2; i++) { \
            int row = rows[i], q = qs[i]; \
            size_t ga = (size_t)(tok0 + row) * DD + (c) * 32 + q * 8; \
            size_t gb = (size_t)row * DD + (c) * 32 + q * 8; \
            int so = row * LDA + q * 8; \
            cp_async16(smem_u32(base + so), &g_xh[ga]); \
            cp_async16(smem_u32(base + L_AST + so), &g_xl[ga]); \
            cp_async16(smem_u32(base + 2 * L_AST + so), &g_phinth[gb]); \
            cp_async16(smem_u32(base + 3 * L_AST + so), &g_phintl[gb]); \
        } \
    } while (0)

    L_LOAD(0, 0);
    CP_COMMIT();
    for (int c = 0; c < 32; c++) {
        if (c < 31) L_LOAD(c + 1, (c + 1) & 1);
        CP_COMMIT();
        CP_WAIT1();
        __syncthreads();
        __nv_bfloat16* sAh = sm_l + (c & 1) * L_SST;
        __nv_bfloat16* sAl = sAh + L_AST;
        __nv_bfloat16* sBh = sAl + L_AST;
        __nv_bfloat16* sBl = sBh + L_AST;
        #pragma unroll
        for (int ks = 0; ks < 2; ks++) {
            uint32_t ah[4][4], al[4][4], bh[4][2], bl[4][2];
            #pragma unroll
            for (int a = 0; a < 4; a++) {
                int off = (wm * 64 + a * 16 + a_row) * LDA + ks * 16 + a_col;
                ldsm_x4(ah[a][0], ah[a][1], ah[a][2], ah[a][3], smem_u32(&sAh[off]));
                ldsm_x4(al[a][0], al[a][1], al[a][2], al[a][3], smem_u32(&sAl[off]));
            }
            #pragma unroll
            for (int p = 0; p < 2; p++) {
                int off = (wn * 32 + p * 16 + b_row) * LDA + ks * 16 + b_col;
                uint32_t r0, r1, r2, r3;
                ldsm_x4(r0, r1, r2, r3, smem_u32(&sBh[off]));
                bh[p * 2][0] = r0; bh[p * 2][1] = r1;
                bh[p * 2 + 1][0] = r2; bh[p * 2 + 1][1] = r3;
                ldsm_x4(r0, r1, r2, r3, smem_u32(&sBl[off]));
                bl[p * 2][0] = r0; bl[p * 2][1] = r1;
                bl[p * 2 + 1][0] = r2; bl[p * 2 + 1][1] = r3;
            }
            #pragma unroll
            for (int a = 0; a < 4; a++)
                #pragma unroll
                for (int n = 0; n < 4; n++) {
                    mma_bf16(acc[a][n], ah[a], bh[n]);
                    mma_bf16(acc[a][n], ah[a], bl[n]);
                    mma_bf16(acc[a][n], al[a], bh[n]);
                }
        }
        __syncthreads();
    }
    // epilogue: exp2, split to bf16 hi/lo; accumulate row/col sums
    int r0 = lane >> 2, c0 = (lane & 3) * 2;
    float rsum[4][2];
    float csum[4][2];
    #pragma unroll
    for (int a = 0; a < 4; a++) { rsum[a][0] = 0.f; rsum[a][1] = 0.f; }
    #pragma unroll
    for (int n = 0; n < 4; n++) { csum[n][0] = 0.f; csum[n][1] = 0.f; }
    #pragma unroll
    for (int a = 0; a < 4; a++) {
        int row = tok0 + wm * 64 + a * 16 + r0;
        float rv0 = g_rinv[row] * LOG2E;
        float rv1 = g_rinv[row + 8] * LOG2E;
        #pragma unroll
        for (int n = 0; n < 4; n++) {
            int col = wn * 32 + n * 8 + c0;
            float e0 = ex2f(acc[a][n][0] * rv0), e1 = ex2f(acc[a][n][1] * rv0);
            float e2 = ex2f(acc[a][n][2] * rv1), e3 = ex2f(acc[a][n][3] * rv1);
            rsum[a][0] += e0 + e1;
            rsum[a][1] += e2 + e3;
            csum[n][0] += e0 + e2;
            csum[n][1] += e1 + e3;
            __nv_bfloat16 h0, l0, h1, l1, h2, l2, h3, l3;
            split1(e0, h0, l0); split1(e1, h1, l1);
            split1(e2, h2, l2); split1(e3, h3, l3);
            *reinterpret_cast<__nv_bfloat162*>(&g_Eh[(size_t)row * NP + col]) =
                __halves2bfloat162(h0, h1);
            *reinterpret_cast<__nv_bfloat162*>(&g_El[(size_t)row * NP + col]) =
                __halves2bfloat162(l0, l1);
            *reinterpret_cast<__nv_bfloat162*>(&g_Eh[(size_t)(row + 8) * NP + col]) =
                __halves2bfloat162(h2, h3);
            *reinterpret_cast<__nv_bfloat162*>(&g_El[(size_t)(row + 8) * NP + col]) =
                __halves2bfloat162(l2, l3);
        }
    }
    float* srow = reinterpret_cast<float*>(sm_l);   // [4 wn][128 rows]
    float* scol = srow + 4 * 128;                   // [2 wm][128 cols]
    __syncthreads();
    #pragma unroll
    for (int a = 0; a < 4; a++)
        #pragma unroll
        for (int h = 0; h < 2; h++) {
            float v = rsum[a][h];
            v += __shfl_xor_sync(0xffffffffu, v, 1);
            v += __shfl_xor_sync(0xffffffffu, v, 2);
            if ((lane & 3) == 0)
                srow[wn * 128 + wm * 64 + a * 16 + h * 8 + r0] = v;
        }
    #pragma unroll
    for (int n = 0; n < 4; n++)
        #pragma unroll
        for (int q1 = 0; q1 < 2; q1++) {
            float v = csum[n][q1];
            v += __shfl_xor_sync(0xffffffffu, v, 4);
            v += __shfl_xor_sync(0xffffffffu, v, 8);
            v += __shfl_xor_sync(0xffffffffu, v, 16);
            if (lane < 4)
                scol[wm * 128 + wn * 32 + n * 8 + lane * 2 + q1] = v;
        }
    __syncthreads();
    if (t < 128) {
        float rs = srow[t] + srow[128 + t] + srow[256 + t] + srow[384 + t];
        g_rsinv[tok0 + t] = 1.0f / rs;
        g_part[blockIdx.x * NP + t] = scol[t] + scol[128 + t];
    }
}

// K4: final column sums per batch (32 m-tiles each)
__global__ void k_colsum() {
    int b = blockIdx.x;
    int np = threadIdx.x;
    float s = 0.f;
    #pragma unroll
    for (int i = 0; i < 32; i++)
        s += g_part[(b * 32 + i) * NP + np];
    g_colsum[b * NP + np] = s;
}

// ===========================================================================
// K5 (mma, cp.async 2-stage): xsp[seg][b][np][d] = sum_{m in seg} E[m][np]*x[m][d]
#define LDE 136
#define X_AST (32 * LDE)
#define X_SST (4 * X_AST)
__global__ __launch_bounds__(256) void k_xs_mma() {
    extern __shared__ __nv_bfloat16 sm_x[];
    int t = threadIdx.x, lane = t & 31, wid = t >> 5;
    int d0 = blockIdx.x * 128;
    int b = blockIdx.y;
    int seg = blockIdx.z;
    int base = b * MM + seg * 1024;
    int wm = wid & 1, wn = wid >> 1;
    float acc[4][4][4];
    #pragma unroll
    for (int a = 0; a < 4; a++)
        #pragma unroll
        for (int n = 0; n < 4; n++)
            #pragma unroll
            for (int q = 0; q < 4; q++) acc[a][n][q] = 0.f;

    int aA_col = ((lane >> 3) & 1) * 8;
    int aA_row = (lane & 7) + (lane >> 4) * 8;
    int aB_row = (lane & 7) + ((lane >> 3) & 1) * 8;
    int aB_col = (lane >> 4) * 8;

    #define X_LOAD(c, s) do { \
        __nv_bfloat16* bb_ = sm_x + (s) * X_SST; \
        _Pragma("unroll") \
        for (int i = 0; i < 2; i++) { \
            int idx = t + i * 256; \
            int row = idx >> 4, q = idx & 15; \
            size_t ge = (size_t)(base + (c) * 32 + row) * NP + q * 8; \
            size_t gx = (size_t)(base + (c) * 32 + row) * DD + d0 + q * 8; \
            int so = row * LDE + q * 8; \
            cp_async16(smem_u32(bb_ + so), &g_Eh[ge]); \
            cp_async16(smem_u32(bb_ + X_AST + so), &g_El[ge]); \
            cp_async16(smem_u32(bb_ + 2 * X_AST + so), &g_xh[gx]); \
            cp_async16(smem_u32(bb_ + 3 * X_AST + so), &g_xl[gx]); \
        } \
    } while (0)

    X_LOAD(0, 0);
    CP_COMMIT();
    for (int c = 0; c < 32; c++) {
        if (c < 31) X_LOAD(c + 1, (c + 1) & 1);
        CP_COMMIT();
        CP_WAIT1();
        __syncthreads();
        __nv_bfloat16* sEh = sm_x + (c & 1) * X_SST;
        __nv_bfloat16* sEl = sEh + X_AST;
        __nv_bfloat16* sXh = sEl + X_AST;
        __nv_bfloat16* sXl = sXh + X_AST;
        #pragma unroll
        for (int ks = 0; ks < 2; ks++) {
            uint32_t ah[4][4], al[4][4], bh[4][2], bl[4][2];
            #pragma unroll
            for (int a = 0; a < 4; a++) {
                int npb = wm * 64 + a * 16 + aA_col;
                int off = (ks * 16 + aA_row) * LDE + npb;
                ldsm_x4t(ah[a][0], ah[a][1], ah[a][2], ah[a][3], smem_u32(&sEh[off]));
                ldsm_x4t(al[a][0], al[a][1], al[a][2], al[a][3], smem_u32(&sEl[off]));
            }
            #pragma unroll
            for (int p = 0; p < 2; p++) {
                int nb = wn * 32 + p * 16 + aB_col;
                int off = (ks * 16 + aB_row) * LDE + nb;
                uint32_t r0, r1, r2, r3;
                ldsm_x4t(r0, r1, r2, r3, smem_u32(&sXh[off]));
                bh[p * 2][0] = r0; bh[p * 2][1] = r1;
                bh[p * 2 + 1][0] = r2; bh[p * 2 + 1][1] = r3;
                ldsm_x4t(r0, r1, r2, r3, smem_u32(&sXl[off]));
                bl[p * 2][0] = r0; bl[p * 2][1] = r1;
                bl[p * 2 + 1][0] = r2; bl[p * 2 + 1][1] = r3;
            }
            #pragma unroll
            for (int a = 0; a < 4; a++)
                #pragma unroll
                for (int n = 0; n < 4; n++) {
                    mma_bf16(acc[a][n], ah[a], bh[n]);
                    mma_bf16(acc[a][n], ah[a], bl[n]);
                    mma_bf16(acc[a][n], al[a], bh[n]);
                }
        }
        __syncthreads();
    }
    int r0 = lane >> 2, c0 = (lane & 3) * 2;
    #pragma unroll
    for (int a = 0; a < 4; a++) {
        int np = wm * 64 + a * 16 + r0;
        #pragma unroll
        for (int n = 0; n < 4; n++) {
            int d = d0 + wn * 32 + n * 8 + c0;
            float* dst0 = &g_xsp[(((size_t)seg * BB + b) * NP + np) * DD + d];
            float* dst1 = &g_xsp[(((size_t)seg * BB + b) * NP + np + 8) * DD + d];
            *reinterpret_cast<float2*>(dst0) = make_float2(acc[a][n][0], acc[a][n][1]);
            *reinterpret_cast<float2*>(dst1) = make_float2(acc[a][n][2], acc[a][n][3]);
        }
    }
}

// ===========================================================================
// K6 (mma): ys[(b,p)][e] = sum_d xs[(b,p)][d] * W[n][d][e] + bias[n][e]
// A built in-kernel from 4-segment xsp sum * 1/colsum (k_xs_reduce folded in).
#define LDW 264
#define LDK 72
__global__ __launch_bounds__(256) void k_ys_mma(const float* __restrict__ W,
                                                const float* __restrict__ bias) {
    extern __shared__ __nv_bfloat16 sm_y[];
    __nv_bfloat16* sWh = sm_y;                 // [64 k][LDW]
    __nv_bfloat16* sWl = sWh + 64 * LDW;
    __nv_bfloat16* sAh = sWl + 64 * LDW;       // [16 m][LDK]
    __nv_bfloat16* sAl = sAh + 16 * LDK;
    int t = threadIdx.x, lane = t & 31, wid = t >> 5;
    int nexp = blockIdx.y;
    int e0 = blockIdx.x * 256;
    float acc[4][4];
    #pragma unroll
    for (int n = 0; n < 4; n++)
        #pragma unroll
        for (int q = 0; q < 4; q++) acc[n][q] = 0.f;

    int a_row = lane & 15;
    int a_col = (lane >> 4) * 8;
    int aB_row = (lane & 7) + ((lane >> 3) & 1) * 8;
    int aB_col = (lane >> 4) * 8;

    // per-thread A-row state (t<128): row = (b,p), with folded reduce
    int arow = t >> 3, aq = t & 7;
    int abb = arow >> 1, ap = arow & 1;
    float ainv = (t < 128) ? 1.0f / g_colsum[abb * NP + nexp * 2 + ap] : 0.f;
    size_t abase = ((size_t)abb * NP + nexp * 2 + ap) * DD + aq * 8;

    for (int c = 0; c < 16; c++) {
        int k0 = c * 64;
        // A: xs rows = (sum_s xsp)/colsum, 16 x 64, fp32 -> hi/lo
        if (t < 128) {
            float v[8];
            {
                const float* s0 = &g_xsp[abase + k0];
                float4 v0 = *reinterpret_cast<const float4*>(s0);
                float4 v1 = *reinterpret_cast<const float4*>(s0 + 4);
                #pragma unroll
                for (int seg = 1; seg < 4; seg++) {
                    const float* ss = &g_xsp[(size_t)seg * BB * NP * DD + abase + k0];
                    float4 w0 = *reinterpret_cast<const float4*>(ss);
                    float4 w1 = *reinterpret_cast<const float4*>(ss + 4);
                    v0.x += w0.x; v0.y += w0.y; v0.z += w0.z; v0.w += w0.w;
                    v1.x += w1.x; v1.y += w1.y; v1.z += w1.z; v1.w += w1.w;
                }
                v[0] = v0.x * ainv; v[1] = v0.y * ainv; v[2] = v0.z * ainv; v[3] = v0.w * ainv;
                v[4] = v1.x * ainv; v[5] = v1.y * ainv; v[6] = v1.z * ainv; v[7] = v1.w * ainv;
            }
            uint32_t hs[8], ls[8];
            #pragma unroll
            for (int j = 0; j < 8; j++) {
                __nv_bfloat16 h, l;
                split1(v[j], h, l);
                hs[j] = (uint32_t)__bfloat16_as_ushort(h);
                ls[j] = (uint32_t)__bfloat16_as_ushort(l);
            }
            uint4 hi = {hs[0] | (hs[1] << 16), hs[2] | (hs[3] << 16),
                        hs[4] | (hs[5] << 16), hs[6] | (hs[7] << 16)};
            uint4 lo = {ls[0] | (ls[1] << 16), ls[2] | (ls[3] << 16),
                        ls[4] | (ls[5] << 16), ls[6] | (ls[7] << 16)};
            *reinterpret_cast<uint4*>(&sAh[arow * LDK + aq * 8]) = hi;
            *reinterpret_cast<uint4*>(&sAl[arow * LDK + aq * 8]) = lo;
        }
        // W: 64 k x 256 e, fp32 -> hi/lo
        #pragma unroll
        for (int i = 0; i < 8; i++) {
            int idx = t + i * 256;
            int row = idx >> 5, q = idx & 31;
            const float* src = &W[((size_t)nexp * DD + k0 + row) * DD + e0 + q * 8];
            float4 v0 = *reinterpret_cast<const float4*>(src);
            float4 v1 = *reinterpret_cast<const float4*>(src + 4);
            float v[8] = {v0.x, v0.y, v0.z, v0.w, v1.x, v1.y, v1.z, v1.w};
            uint32_t hs[8], ls[8];
            #pragma unroll
            for (int j = 0; j < 8; j++) {
                __nv_bfloat16 h, l;
                split1(v[j], h, l);
                hs[j] = (uint32_t)__bfloat16_as_ushort(h);
                ls[j] = (uint32_t)__bfloat16_as_ushort(l);
            }
            uint4 hi = {hs[0] | (hs[1] << 16), hs[2] | (hs[3] << 16),
                        hs[4] | (hs[5] << 16), hs[6] | (hs[7] << 16)};
            uint4 lo = {ls[0] | (ls[1] << 16), ls[2] | (ls[3] << 16),
                        ls[4] | (ls[5] << 16), ls[6] | (ls[7] << 16)};
            *reinterpret_cast<uint4*>(&sWh[row * LDW + q * 8]) = hi;
            *reinterpret_cast<uint4*>(&sWl[row * LDW + q * 8]) = lo;
        }
        __syncthreads();
        #pragma unroll
        for (int ks = 0; ks < 4; ks++) {
            uint32_t ah[4], al[4], bh[4][2], bl[4][2];
            {
                int off = a_row * LDK + ks * 16 + a_col;
                ldsm_x4(ah[0], ah[1], ah[2], ah[3], smem_u32(&sAh[off]));
                ldsm_x4(al[0], al[1], al[2], al[3], smem_u32(&sAl[off]));
            }
            #pragma unroll
            for (int p = 0; p < 2; p++) {
                int nb = wid * 32 + p * 16 + aB_col;
                int off = (ks * 16 + aB_row) * LDW + nb;
                uint32_t r0, r1, r2, r3;
                ldsm_x4t(r0, r1, r2, r3, smem_u32(&sWh[off]));
                bh[p * 2][0] = r0; bh[p * 2][1] = r1;
                bh[p * 2 + 1][0] = r2; bh[p * 2 + 1][1] = r3;
                ldsm_x4t(r0, r1, r2, r3, smem_u32(&sWl[off]));
                bl[p * 2][0] = r0; bl[p * 2][1] = r1;
                bl[p * 2 + 1][0] = r2; bl[p * 2 + 1][1] = r3;
            }
            #pragma unroll
            for (int n = 0; n < 4; n++) {
                mma_bf16(acc[n], ah, bh[n]);
                mma_bf16(acc[n], ah, bl[n]);
                mma_bf16(acc[n], al, bh[n]);
            }
        }
        __syncthreads();
    }
    // epilogue: + bias, split hi/lo, store
    int r0 = lane >> 2, c0 = (lane & 3) * 2;
    #pragma unroll
    for (int n = 0; n < 4; n++) {
        int e = e0 + wid * 32 + n * 8 + c0;
        float2 bv = *reinterpret_cast<const float2*>(&bias[nexp * DD + e]);
        #pragma unroll
        for (int h = 0; h < 2; h++) {
            int row = r0 + h * 8;              // (b,p)
            int bb = row >> 1, p = row & 1;
            float v0 = acc[n][h * 2 + 0] + bv.x;
            float v1 = acc[n][h * 2 + 1] + bv.y;
            __nv_bfloat16 h0, l0, h1, l1;
            split1(v0, h0, l0); split1(v1, h1, l1);
            size_t o = ((size_t)bb * NP + nexp * 2 + p) * DD + e;
            *reinterpret_cast<__nv_bfloat162*>(&g_ysh[o]) = __halves2bfloat162(h0, h1);
            *reinterpret_cast<__nv_bfloat162*>(&g_ysl[o]) = __halves2bfloat162(l0, l1);
        }
    }
}

// ===========================================================================
// K7 (mma, cp.async 2-stage): y[m][d] = rsinv[m]*sum_np E[m][np]*ys[np][d] + x[m][d]
// K = np = 128 in 4 chunks of 32.
#define C_ASZ (128 * LDA)          // A array elems per stage (hi or lo)
#define C_BSZ (32 * LDE)           // B array elems per stage
#define C_SST (2 * C_ASZ + 2 * C_BSZ)
__global__ __launch_bounds__(256) void k_combine_mma(const float* __restrict__ x,
                                                     float* __restrict__ y) {
    extern __shared__ __nv_bfloat16 sm_c[];
    int t = threadIdx.x, lane = t & 31, wid = t >> 5;
    int b = blockIdx.z;
    int tokbase = b * MM + blockIdx.x * 128;
    int d0 = blockIdx.y * 128;
    int wm = wid & 1, wn = wid >> 1;
    float acc[4][4][4];
    #pragma unroll
    for (int a = 0; a < 4; a++)
        #pragma unroll
        for (int n = 0; n < 4; n++)
            #pragma unroll
            for (int q = 0; q < 4; q++) acc[a][n][q] = 0.f;

    int a_row = lane & 15;
    int a_col = (lane >> 4) * 8;
    int aB_row = (lane & 7) + ((lane >> 3) & 1) * 8;
    int aB_col = (lane >> 4) * 8;

    #define C_LOAD(c, s) do { \
        __nv_bfloat16* base = sm_c + (s) * C_SST; \
        _Pragma("unroll") \
        for (int i = 0; i < 2; i++) { \
            int idx = t + i * 256; \
            int row = idx >> 2, q = idx & 3; \
            size_t ge = (size_t)(tokbase + row) * NP + (c) * 32 + q * 8; \
            int so = row * LDA + q * 8; \
            cp_async16(smem_u32(base + so), &g_Eh[ge]); \
            cp_async16(smem_u32(base + C_ASZ + so), &g_El[ge]); \
            int rowb = idx >> 4, qb = idx & 15; \
            size_t gy = ((size_t)b * NP + (c) * 32 + rowb) * DD + d0 + qb * 8; \
            int sob = rowb * LDE + qb * 8; \
            cp_async16(smem_u32(base + 2 * C_ASZ + sob), &g_ysh[gy]); \
            cp_async16(smem_u32(base + 2 * C_ASZ + C_BSZ + sob), &g_ysl[gy]); \
        } \
    } while (0)

    C_LOAD(0, 0);
    CP_COMMIT();
    for (int c = 0; c < 4; c++) {
        if (c < 3) C_LOAD(c + 1, (c + 1) & 1);
        CP_COMMIT();
        CP_WAIT1();
        __syncthreads();
        __nv_bfloat16* sAh = sm_c + (c & 1) * C_SST;
        __nv_bfloat16* sAl = sAh + C_ASZ;
        __nv_bfloat16* sBh = sAl + C_ASZ;
        __nv_bfloat16* sBl = sBh + C_BSZ;
        #pragma unroll
        for (int ks = 0; ks < 2; ks++) {
            uint32_t ah[4][4], al[4][4], bh[4][2], bl[4][2];
            #pragma unroll
            for (int a = 0; a < 4; a++) {
                int off = (wm * 64 + a * 16 + a_row) * LDA + ks * 16 + a_col;
                ldsm_x4(ah[a][0], ah[a][1], ah[a][2], ah[a][3], smem_u32(&sAh[off]));
                ldsm_x4(al[a][0], al[a][1], al[a][2], al[a][3], smem_u32(&sAl[off]));
            }
            #pragma unroll
            for (int p = 0; p < 2; p++) {
                int nb = wn * 32 + p * 16 + aB_col;
                int off = (ks * 16 + aB_row) * LDE + nb;
                uint32_t r0, r1, r2, r3;
                ldsm_x4t(r0, r1, r2, r3, smem_u32(&sBh[off]));
                bh[p * 2][0] = r0; bh[p * 2][1] = r1;
                bh[p * 2 + 1][0] = r2; bh[p * 2 + 1][1] = r3;
                ldsm_x4t(r0, r1, r2, r3, smem_u32(&sBl[off]));
                bl[p * 2][0] = r0; bl[p * 2][1] = r1;
                bl[p * 2 + 1][0] = r2; bl[p * 2 + 1][1] = r3;
            }
            #pragma unroll
            for (int a = 0; a < 4; a++)
                #pragma unroll
                for (int n = 0; n < 4; n++) {
                    mma_bf16(acc[a][n], ah[a], bh[n]);
                    mma_bf16(acc[a][n], ah[a], bl[n]);
                    mma_bf16(acc[a][n], al[a], bh[n]);
                }
        }
        __syncthreads();
    }
    int r0 = lane >> 2, c0 = (lane & 3) * 2;
    #pragma unroll
    for (int a = 0; a < 4; a++) {
        int m0 = tokbase + wm * 64 + a * 16 + r0;
        float rs0 = g_rsinv[m0];
        float rs1 = g_rsinv[m0 + 8];
        #pragma unroll
        for (int n = 0; n < 4; n++) {
            int d = d0 + wn * 32 + n * 8 + c0;
            size_t i0 = (size_t)m0 * DD + d;
            size_t i1 = (size_t)(m0 + 8) * DD + d;
            float2 xv0 = *reinterpret_cast<const float2*>(&x[i0]);
            float2 xv1 = *reinterpret_cast<const float2*>(&x[i1]);
            *reinterpret_cast<float2*>(&y[i0]) =
                make_float2(acc[a][n][0] * rs0 + xv0.x, acc[a][n][1] * rs0 + xv0.y);
            *reinterpret_cast<float2*>(&y[i1]) =
                make_float2(acc[a][n][2] * rs1 + xv1.x, acc[a][n][3] * rs1 + xv1.y);
        }
    }
}

// ---------------------------------------------------------------------------
extern "C" void kernel_launch(void* const* d_in, const int* in_sizes, int n_in,
                              void* d_out, int out_size) {
    const float* x     = (const float*)d_in[0];  // [8,4096,1024]
    const float* phi   = (const float*)d_in[1];  // [1024,64,2]
    const float* scale = (const float*)d_in[2];  // [1]
    const float* W     = (const float*)d_in[3];  // [64,1024,1024]
    const float* bias  = (const float*)d_in[4];  // [64,1024]
    float* y = (float*)d_out;                    // [8,4096,1024]

    const int smem_logits  = 2 * L_SST * 2;                         // 81920
    const int smem_xs      = 2 * X_SST * 2;                         // 69632
    const int smem_ys      = 2 * 64 * LDW * 2 + 2 * 16 * LDK * 2;   // 72192
    const int smem_combine = 2 * C_SST * 2;                         // 75776
    cudaFuncSetAttribute(k_logits_mma, cudaFuncAttributeMaxDynamicSharedMemorySize, smem_logits);
    cudaFuncSetAttribute(k_xs_mma, cudaFuncAttributeMaxDynamicSharedMemorySize, smem_xs);
    cudaFuncSetAttribute(k_ys_mma, cudaFuncAttributeMaxDynamicSharedMemorySize, smem_ys);
    cudaFuncSetAttribute(k_combine_mma, cudaFuncAttributeMaxDynamicSharedMemorySize, smem_combine);

    k_phinorm<<<NP, 256>>>(phi, scale);
    k_rinv<<<BM / 8, 256>>>(x);
    k_logits_mma<<<BM / 128, 256, smem_logits>>>();
    k_colsum<<<BB, NP>>>();
    k_xs_mma<<<dim3(8, BB, 4), 256, smem_xs>>>();
    k_ys_mma<<<dim3(4, NEXP), 256, smem_ys>>>(W, bias);
    k_combine_mma<<<dim3(32, 8, BB), 256, smem_combine>>>(x, y);
}